// round 10
// baseline (speedup 1.0000x reference)
#include <cuda_runtime.h>
#include <cstdint>

#define SQ   2048
#define BB   4
#define DIM  1024
#define NH   16
#define NDQK 20
#define NDV  64
#define DLQ  256
#define DLKV 128
#define NTOK (BB*SQ)

__device__ float g_hrnd[(size_t)NTOK*DIM];
__device__ float g_projcat[(size_t)NTOK*384];
__device__ float g_qlat[NTOK*DLQ];
__device__ float g_kvn [NTOK*DLKV];
__device__ float g_qkv [(size_t)NTOK*NH*DLKV];
__device__ float g_v   [(size_t)NTOK*NH*NDV];
__device__ float g_wc  [NH*DLKV*DLQ];
__device__ float g_biasc[NH*DLKV];
__device__ float g_worn[DIM*NH*NDV];
__device__ float g_wkvbv[NH*NDV*DLKV];
__device__ float g_wcat[384*DIM];
__device__ float g_bcat[384];

// ======================= helpers =======================
__device__ __forceinline__ uint32_t f2tf(float f){
    uint32_t u; asm("cvt.rna.tf32.f32 %0, %1;" : "=r"(u) : "f"(f)); return u;
}
__device__ __forceinline__ float rnd(float f){ return __uint_as_float(f2tf(f)); }
__device__ __forceinline__ void mma8(float&c0,float&c1,float&c2,float&c3,
    uint32_t a0,uint32_t a1,uint32_t a2,uint32_t a3,uint32_t b0,uint32_t b1){
    asm volatile("mma.sync.aligned.m16n8k8.row.col.f32.tf32.tf32.f32 "
        "{%0,%1,%2,%3}, {%4,%5,%6,%7}, {%8,%9}, {%0,%1,%2,%3};"
        : "+f"(c0),"+f"(c1),"+f"(c2),"+f"(c3)
        : "r"(a0),"r"(a1),"r"(a2),"r"(a3),"r"(b0),"r"(b1));
}
__device__ __forceinline__ void ldsm4(uint32_t&r0,uint32_t&r1,uint32_t&r2,uint32_t&r3,uint32_t a){
    asm volatile("ldmatrix.sync.aligned.m8n8.x4.shared.b16 {%0,%1,%2,%3}, [%4];"
        : "=r"(r0),"=r"(r1),"=r"(r2),"=r"(r3) : "r"(a));
}
__device__ __forceinline__ uint32_t smem_u32(const void* p){
    uint32_t a;
    asm("{ .reg .u64 t; cvta.to.shared.u64 t, %1; cvt.u32.u64 %0, t; }" : "=r"(a) : "l"(p));
    return a;
}
__device__ __forceinline__ void cp16(uint32_t dst, const void* src){
    asm volatile("cp.async.cg.shared.global [%0], [%1], 16;" :: "r"(dst), "l"(src));
}
__device__ __forceinline__ void cp_commit(){ asm volatile("cp.async.commit_group;" ::: "memory"); }
template<int NW> __device__ __forceinline__ void cp_wait(){
    asm volatile("cp.async.wait_group %0;" :: "n"(NW) : "memory");
}
__device__ __forceinline__ uint32_t ldb(const float* p){ return __float_as_uint(*p); }

// ---------- prep ----------
__global__ void round_copy(const float* __restrict__ in, float* __restrict__ out){
    size_t i = ((size_t)blockIdx.x*256 + threadIdx.x)*4;
    float4 v = *(const float4*)&in[i];
    v.x=rnd(v.x); v.y=rnd(v.y); v.z=rnd(v.z); v.w=rnd(v.w);
    *(float4*)&out[i] = v;
}
__global__ void prep_wkvbv(const float* __restrict__ wkv_b_w, float* __restrict__ outp){
    int i = blockIdx.x*256 + threadIdx.x;          // over NH*64*128
    int h = i >> 13, rem = i & 8191;
    outp[i] = rnd(wkv_b_w[(size_t)(h*(NDQK+NDV) + NDQK)*DLKV + rem]);
}
__global__ void prep_wcat(const float* __restrict__ wq_a_w, const float* __restrict__ wq_a_b,
                          const float* __restrict__ wkv_a_w, const float* __restrict__ wkv_a_b,
                          float* __restrict__ wcat, float* __restrict__ bcat){
    int n = blockIdx.x;
    const float* src = (n < 256) ? (wq_a_w + (size_t)n*DIM) : (wkv_a_w + (size_t)(n-256)*DIM);
    for (int k = threadIdx.x; k < DIM; k += 256) wcat[(size_t)n*DIM + k] = rnd(src[k]);
    if (threadIdx.x == 0) bcat[n] = (n < 256) ? wq_a_b[n] : wkv_a_b[n-256];
}
__global__ void prep_wc_kernel(const float* __restrict__ wq_b_w,
                               const float* __restrict__ wq_b_b,
                               const float* __restrict__ wkv_b_w,
                               float* __restrict__ wc, float* __restrict__ biasc) {
    int hc = blockIdx.x, h = hc >> 7, c = hc & 127, l = threadIdx.x;
    float acc = 0.f, accb = 0.f;
    #pragma unroll
    for (int q = 0; q < NDQK; q++) {
        float kb = wkv_b_w[(size_t)(h*(NDQK+NDV) + q)*DLKV + c];
        acc  = fmaf(kb, wq_b_w[(size_t)(h*NDQK + q)*DLQ + l], acc);
        accb = fmaf(kb, wq_b_b[h*NDQK + q], accb);
    }
    wc[(size_t)hc*DLQ + l] = rnd(acc);
    if (l == 0) biasc[hc] = accb;
}

// ---------- RMSNorm ----------
__global__ void rms_kernel(const float* __restrict__ in, int ld, int off,
                           const float* __restrict__ w, float* __restrict__ out, int N) {
    int row = blockIdx.x;
    const float* x = in + (size_t)row*ld + off;
    float ss = 0.f;
    for (int i = threadIdx.x; i < N; i += 128) { float v = x[i]; ss = fmaf(v, v, ss); }
    #pragma unroll
    for (int d = 16; d; d >>= 1) ss += __shfl_xor_sync(0xffffffffu, ss, d);
    __shared__ float red[4];
    if ((threadIdx.x & 31) == 0) red[threadIdx.x >> 5] = ss;
    __syncthreads();
    float r = rsqrtf((red[0]+red[1]+red[2]+red[3]) / (float)N + 1e-6f);
    for (int i = threadIdx.x; i < N; i += 128)
        out[(size_t)row*N + i] = rnd(x[i] * r * w[i]);
}

// ---------- tf32 mma GEMM, cp.async 3-stage, ldmatrix, z-batched ----------
template<int BN, bool ROUND, bool BIAS>
__global__ __launch_bounds__(256, 2) void tgemm3(
    const float* __restrict__ A, int lda, size_t sAz,
    const float* __restrict__ Bm, int ldb, size_t sBz,
    const float* __restrict__ bias, float* __restrict__ C, int ldc, size_t sCz,
    int K)
{
    extern __shared__ float smem[];
    const int SSZ = (128+BN)*36;
    constexpr int NJ = BN/16;
    constexpr int NP = BN/32;

    const int mt = blockIdx.y*128, nt = blockIdx.x*BN;
    A  += (size_t)blockIdx.z*sAz;
    Bm += (size_t)blockIdx.z*sBz;
    C  += (size_t)blockIdx.z*sCz;

    const int tid = threadIdx.x, w = tid>>5, lane = tid&31;
    const int g = lane>>2, t = lane&3;
    const int wm = (w&3)*32, wn = (w>>2)*(BN/2);
    const int mat = lane>>3, r8 = lane&7;
    const int matr = mat&1, matc = mat>>1;

    const uint32_t smu = smem_u32(smem);
    const uint32_t aoff0 = (uint32_t)(((wm + matr*8 + r8)*36 + matc*4)*4);
    const uint32_t boff0 = (uint32_t)((128*36 + (wn + matc*8 + r8)*36 + matr*4)*4);

    float acc[2][NJ][4];
    #pragma unroll
    for (int i=0;i<2;i++)
        #pragma unroll
        for (int j=0;j<NJ;j++){ acc[i][j][0]=0.f; acc[i][j][1]=0.f; acc[i][j][2]=0.f; acc[i][j][3]=0.f; }

    const int NC = K >> 5;
    auto fetch = [&](int i, int slot){
        const int k0 = i << 5;
        float* dA = smem + slot*SSZ;
        float* dB = dA + 128*36;
        #pragma unroll
        for (int s2=0;s2<4;s2++){
            int v = tid + s2*256, r = v>>3, c4 = (v&7)<<2;
            cp16(smem_u32(&dA[r*36 + c4]), &A[(size_t)(mt+r)*lda + k0 + c4]);
        }
        #pragma unroll
        for (int s2=0;s2<BN/32;s2++){
            int v = tid + s2*256, r = v>>3, c4 = (v&7)<<2;
            cp16(smem_u32(&dB[r*36 + c4]), &Bm[(size_t)(nt+r)*ldb + k0 + c4]);
        }
        cp_commit();
    };
    fetch(0, 0);
    if (NC > 1) fetch(1, 1);

    for (int i=0;i<NC;i++){
        if (i == NC-1) cp_wait<0>(); else cp_wait<1>();
        __syncthreads();
        if (i+2 < NC) fetch(i+2, (i+2)%3);
        const uint32_t sb = smu + (uint32_t)((i%3)*SSZ*4);
        #pragma unroll
        for (int kk=0; kk<32; kk+=8){
            uint32_t af[2][4], bf[NJ][2];
            #pragma unroll
            for (int ii=0;ii<2;ii++)
                ldsm4(af[ii][0],af[ii][1],af[ii][2],af[ii][3],
                      sb + aoff0 + (uint32_t)(ii*16*36*4 + kk*4));
            #pragma unroll
            for (int p=0;p<NP;p++){
                uint32_t r0,r1,r2,r3;
                ldsm4(r0,r1,r2,r3, sb + boff0 + (uint32_t)(p*16*36*4 + kk*4));
                bf[2*p][0]=r0; bf[2*p][1]=r1; bf[2*p+1][0]=r2; bf[2*p+1][1]=r3;
            }
            #pragma unroll
            for (int ii=0;ii<2;ii++)
                #pragma unroll
                for (int j=0;j<NJ;j++)
                    mma8(acc[ii][j][0],acc[ii][j][1],acc[ii][j][2],acc[ii][j][3],
                         af[ii][0],af[ii][1],af[ii][2],af[ii][3],bf[j][0],bf[j][1]);
        }
    }
    #pragma unroll
    for (int ii=0;ii<2;ii++){
        int row0 = mt + wm + ii*16 + g, row1 = row0 + 8;
        #pragma unroll
        for (int j=0;j<NJ;j++){
            int col = nt + wn + j*8 + 2*t;
            float b0v = BIAS ? bias[col] : 0.f, b1v = BIAS ? bias[col+1] : 0.f;
            float o00 = acc[ii][j][0]+b0v, o01 = acc[ii][j][1]+b1v;
            float o10 = acc[ii][j][2]+b0v, o11 = acc[ii][j][3]+b1v;
            if (ROUND){ o00=rnd(o00); o01=rnd(o01); o10=rnd(o10); o11=rnd(o11); }
            *(float2*)&C[(size_t)row0*ldc + col] = make_float2(o00, o01);
            *(float2*)&C[(size_t)row1*ldc + col] = make_float2(o10, o11);
        }
    }
}

// ---------- flash attention: 128-row q tiles, fused value projection ----------
// 256 threads / 8 warps. Warp w: softmax rows [w*16, w*16+16), PV cols [w*16, w*16+16).
__global__ __launch_bounds__(256, 1) void attn_tc(
    const float* __restrict__ qkv, const float* __restrict__ kvn,
    const float* __restrict__ wkvbv, float* __restrict__ vout)
{
    extern __shared__ float smf[];
    float*    sKV = smf;                          // [2][64][132]
    uint32_t* sP  = (uint32_t*)(smf + 2*64*132);  // [128][68] tf32 bits
    float*    sAl = smf + 2*64*132 + 128*68;      // [128] alpha
    float*    sL  = sAl + 128;                    // [128] sum

    const int qt = (int)gridDim.x - 1 - (int)blockIdx.x;
    const int h = blockIdx.y, b = blockIdx.z;
    const int tid = threadIdx.x, w = tid>>5, lane = tid & 31;
    const int g = lane >> 2, t = lane & 3;
    const int mat = lane>>3, r8 = lane&7;
    const int matr = mat&1, matc = mat>>1;
    const int q0 = qt*128;
    const int mrow = w*16 + g;            // softmax rows (and +8)
    const int wn = w*16;                  // PV column ownership (16 cols)
    const float scale = 0.22360679774997896f;
    const int KT = 2*qt + 2;              // 64-row KV tiles

    const uint32_t kvu = smem_u32(sKV);
    const uint32_t pu  = smem_u32(sP);
    const uint32_t koff0 = (uint32_t)(((matc*8 + r8)*132 + matr*4)*4);       // B-frag in KV layout
    const uint32_t poff0 = (uint32_t)(((matr*8 + r8)*68 + matc*4)*4);        // A-frag in P layout
    const uint32_t ooff0 = (uint32_t)(((w*16 + matr*8 + r8)*132 + matc*4)*4);// A-frag in staged O

    // prefetch KV tile 0
    {
        #pragma unroll
        for (int s2=0;s2<8;s2++){
            int v = tid + s2*256, r = v>>5, c4 = (v&31)<<2;
            cp16(smem_u32(&sKV[r*132 + c4]), &kvn[((size_t)(b*SQ + r))*128 + c4]);
        }
        cp_commit();
    }
    // Q fragments from gmem (pre-rounded)
    uint32_t qf[16][4];
    {
        const float* qb = &qkv[((size_t)((b*SQ + q0)*NH + h))*128];
        const size_t rs = (size_t)NH*128;
        #pragma unroll
        for (int kk = 0; kk < 16; kk++) {
            qf[kk][0] = ldb(qb + (size_t)(mrow  )*rs + kk*8 + t);
            qf[kk][1] = ldb(qb + (size_t)(mrow+8)*rs + kk*8 + t);
            qf[kk][2] = ldb(qb + (size_t)(mrow  )*rs + kk*8 + t + 4);
            qf[kk][3] = ldb(qb + (size_t)(mrow+8)*rs + kk*8 + t + 4);
        }
    }

    float o[8][2][4];   // [m-tile (16 rows)][8-col group within warp's 16 cols][frag]
    #pragma unroll
    for (int mi=0;mi<8;mi++)
        #pragma unroll
        for (int j=0;j<2;j++){ o[mi][j][0]=0.f; o[mi][j][1]=0.f; o[mi][j][2]=0.f; o[mi][j][3]=0.f; }
    float m0=-1e30f, m1=-1e30f, l0=0.f, l1=0.f;

    for (int kt = 0; kt < KT; kt++) {
        const int st = kt & 1;
        __syncthreads();                 // prev PV done: buffer (1-st) free, P rewritable
        {
            float* dst = sKV + (1-st)*64*132;
            const float* src = (kt < KT-1)
                ? &kvn[((size_t)(b*SQ + (kt+1)*64))*128]
                : &wkvbv[(size_t)h*NDV*DLKV];           // last iter: prefetch W
            #pragma unroll
            for (int s2=0;s2<8;s2++){
                int v = tid + s2*256, r = v>>5, c4 = (v&31)<<2;
                cp16(smem_u32(&dst[r*132 + c4]), src + (size_t)r*128 + c4);
            }
            cp_commit();
            cp_wait<1>();
        }
        __syncthreads();
        const float* cKV = sKV + st*64*132;
        const uint32_t kB = kvu + (uint32_t)(st*64*132*4);
        const int k0 = kt*64;

        // S = Q @ K^T : warp computes its 16 rows x 64 cols
        float s[8][4];
        #pragma unroll
        for (int j = 0; j < 8; j++) { s[j][0]=0.f; s[j][1]=0.f; s[j][2]=0.f; s[j][3]=0.f; }
        #pragma unroll
        for (int kk = 0; kk < 16; kk++) {
            uint32_t bf[8][2];
            #pragma unroll
            for (int p=0;p<4;p++){
                uint32_t r0,r1,r2,r3;
                ldsm4(r0,r1,r2,r3, kB + koff0 + (uint32_t)(p*16*132*4 + kk*8*4));
                bf[2*p][0]=r0; bf[2*p][1]=r1; bf[2*p+1][0]=r2; bf[2*p+1][1]=r3;
            }
            #pragma unroll
            for (int j = 0; j < 8; j++)
                mma8(s[j][0],s[j][1],s[j][2],s[j][3], qf[kk][0],qf[kk][1],qf[kk][2],qf[kk][3],
                     bf[j][0],bf[j][1]);
        }

        // softmax
        const bool diag = (kt >= 2*qt);
        const int grow0 = q0 + mrow, grow1 = grow0 + 8;
        float mx0=-1e30f, mx1=-1e30f;
        #pragma unroll
        for (int j = 0; j < 8; j++) {
            int c = k0 + j*8 + 2*t;
            #pragma unroll
            for (int e = 0; e < 2; e++) {
                float v0 = s[j][e]*scale, v1 = s[j][2+e]*scale;
                if (diag && (c+e) > grow0) v0 = -1e30f;
                if (diag && (c+e) > grow1) v1 = -1e30f;
                s[j][e] = v0; s[j][2+e] = v1;
                mx0 = fmaxf(mx0, v0); mx1 = fmaxf(mx1, v1);
            }
        }
        mx0 = fmaxf(mx0, __shfl_xor_sync(0xffffffffu, mx0, 1));
        mx0 = fmaxf(mx0, __shfl_xor_sync(0xffffffffu, mx0, 2));
        mx1 = fmaxf(mx1, __shfl_xor_sync(0xffffffffu, mx1, 1));
        mx1 = fmaxf(mx1, __shfl_xor_sync(0xffffffffu, mx1, 2));
        float nm0 = fmaxf(m0, mx0), nm1 = fmaxf(m1, mx1);
        float al0 = __expf(m0 - nm0), al1 = __expf(m1 - nm1);
        m0 = nm0; m1 = nm1;
        float ls0 = 0.f, ls1 = 0.f;
        #pragma unroll
        for (int j = 0; j < 8; j++) {
            float p00 = __expf(s[j][0]-nm0), p01 = __expf(s[j][1]-nm0);
            float p10 = __expf(s[j][2]-nm1), p11 = __expf(s[j][3]-nm1);
            ls0 += p00 + p01; ls1 += p10 + p11;
            int c = j*8 + 2*t;
            sP[(mrow  )*68 + c] = f2tf(p00); sP[(mrow  )*68 + c+1] = f2tf(p01);
            sP[(mrow+8)*68 + c] = f2tf(p10); sP[(mrow+8)*68 + c+1] = f2tf(p11);
        }
        ls0 += __shfl_xor_sync(0xffffffffu, ls0, 1);
        ls0 += __shfl_xor_sync(0xffffffffu, ls0, 2);
        ls1 += __shfl_xor_sync(0xffffffffu, ls1, 1);
        ls1 += __shfl_xor_sync(0xffffffffu, ls1, 2);
        l0 = l0*al0 + ls0; l1 = l1*al1 + ls1;
        if (t == 0){ sAl[mrow] = al0; sAl[mrow+8] = al1; }
        __syncthreads();

        // PV column-partitioned: warp owns cols [wn, wn+16) for ALL 128 rows
        #pragma unroll
        for (int mi=0;mi<8;mi++){
            float alo = sAl[mi*16+g], ahi = sAl[mi*16+8+g];
            #pragma unroll
            for (int j=0;j<2;j++){
                o[mi][j][0]*=alo; o[mi][j][1]*=alo;
                o[mi][j][2]*=ahi; o[mi][j][3]*=ahi;
            }
        }
        #pragma unroll
        for (int kb = 0; kb < 64; kb += 8) {
            uint32_t b0a = ldb(&cKV[(kb+t  )*132 + wn + g]);
            uint32_t b1a = ldb(&cKV[(kb+t+4)*132 + wn + g]);
            uint32_t b0b = ldb(&cKV[(kb+t  )*132 + wn + 8 + g]);
            uint32_t b1b = ldb(&cKV[(kb+t+4)*132 + wn + 8 + g]);
            #pragma unroll
            for (int mi=0;mi<8;mi++){
                uint32_t p0,p1,p2,p3;
                ldsm4(p0,p1,p2,p3, pu + poff0 + (uint32_t)(mi*16*68*4 + kb*4));
                mma8(o[mi][0][0],o[mi][0][1],o[mi][0][2],o[mi][0][3], p0,p1,p2,p3, b0a,b1a);
                mma8(o[mi][1][0],o[mi][1][1],o[mi][1][2],o[mi][1][3], p0,p1,p2,p3, b0b,b1b);
            }
        }
    }

    // ---------- fused value projection epilogue ----------
    const int stO = (KT-1) & 1;           // buffer of last KV tile -> reuse for O staging
    if (t == 0){ sL[mrow] = l0; sL[mrow+8] = l1; }
    __syncthreads();                      // all PV done, sL visible
    {
        float* sO = sKV + stO*64*132;     // note: holds 128 rows? NO -> use full 2-buffer trick below
        // Stage normalized O: rows 0..127. Buffer stO has 64*132 floats = rows 0..63 only.
        // Use layout: row r -> sKV[(r&63)*132 + (r>>6)*?]. Instead use stride trick:
        // store 128 rows x 132 across BOTH halves is impossible (W occupies 1-stO).
        // Solution: stage O as [128][68]? K=128 needs 128 cols. -> stage O in sP region
        // is too small. So: do vproj in TWO row-halves, staging 64 rows at a time.
        (void)sO;
    }
    // W is in buffer (1-stO) after cp_wait<0>
    cp_wait<0>();
    const uint32_t wB = kvu + (uint32_t)((1-stO)*64*132*4);
    float* sO = sKV + stO*64*132;
    const uint32_t oB = kvu + (uint32_t)(stO*64*132*4);
    const float* qkv_unused = qkv; (void)qkv_unused;

    #pragma unroll
    for (int half = 0; half < 2; half++){
        __syncthreads();                  // prev half's MMA reads done / sL ready
        // stage rows [half*64, half*64+64): warp w's o rows mi*16+g where mi in [half*4, half*4+4)
        #pragma unroll
        for (int mi2=0;mi2<4;mi2++){
            int mi = half*4 + mi2;
            int lr0 = mi*16 + g, lr1 = lr0 + 8;
            float inv0 = 1.f/sL[lr0], inv1 = 1.f/sL[lr1];
            int sr0 = lr0 - half*64, sr1 = lr1 - half*64;
            #pragma unroll
            for (int j=0;j<2;j++){
                int col = wn + j*8 + 2*t;
                *(float2*)&sO[sr0*132 + col] = make_float2(rnd(o[mi][j][0]*inv0), rnd(o[mi][j][1]*inv0));
                *(float2*)&sO[sr1*132 + col] = make_float2(rnd(o[mi][j][2]*inv1), rnd(o[mi][j][3]*inv1));
            }
        }
        __syncthreads();                  // staged O visible
        // vproj: out[64 rows of this half][64 cols] ; 8 warps: warp w does rows [w*8, w*8+8)?
        // keep 16-row granularity: warps 0..3 do rows 0..63 of this half (w&3)*16, warps 4..7 idle-split cols:
        // simpler: each warp w computes rows ((w&3)*16) of half, cols (w>>2)*32 .. +32.
        {
            const int rw = (w & 3)*16;            // row offset within half
            const int cw = (w >> 2)*32;           // col offset (NDV=64 split in 2)
            const uint32_t aoffO = (uint32_t)(((rw + matr*8 + r8)*132 + matc*4)*4);
            float vo[4][4];
            #pragma unroll
            for (int j=0;j<4;j++){ vo[j][0]=0.f; vo[j][1]=0.f; vo[j][2]=0.f; vo[j][3]=0.f; }
            #pragma unroll
            for (int kk=0; kk<16; kk++){
                uint32_t a0,a1,a2,a3;
                ldsm4(a0,a1,a2,a3, oB + aoffO + (uint32_t)(kk*8*4));
                uint32_t wf[4][2];
                #pragma unroll
                for (int p=0;p<2;p++){
                    uint32_t r0,r1,r2,r3;
                    ldsm4(r0,r1,r2,r3, wB + koff0 + (uint32_t)((cw/16*16 + p*16)*132*4 + kk*8*4));
                    wf[2*p][0]=r0; wf[2*p][1]=r1; wf[2*p+1][0]=r2; wf[2*p+1][1]=r3;
                }
                #pragma unroll
                for (int j=0;j<4;j++)
                    mma8(vo[j][0],vo[j][1],vo[j][2],vo[j][3], a0,a1,a2,a3, wf[j][0],wf[j][1]);
            }
            int grow = q0 + half*64 + rw + g;
            #pragma unroll
            for (int j=0;j<4;j++){
                int col = h*NDV + cw + j*8 + 2*t;
                size_t base0 = (size_t)(b*SQ + grow    )*(NH*NDV) + col;
                size_t base1 = (size_t)(b*SQ + grow + 8)*(NH*NDV) + col;
                *(float2*)&vout[base0] = make_float2(rnd(vo[j][0]), rnd(vo[j][1]));
                *(float2*)&vout[base1] = make_float2(rnd(vo[j][2]), rnd(vo[j][3]));
            }
        }
    }
}

// ---------- launch ----------
extern "C" void kernel_launch(void* const* d_in, const int* in_sizes, int n_in,
                              void* d_out, int out_size)
{
    const float* h_ptr     = (const float*)d_in[0];
    const float* wq_a_w    = (const float*)d_in[2];
    const float* wq_a_b    = (const float*)d_in[3];
    const float* q_norm_w  = (const float*)d_in[4];
    const float* wq_b_w    = (const float*)d_in[5];
    const float* wq_b_b    = (const float*)d_in[6];
    const float* wkv_a_w   = (const float*)d_in[7];
    const float* wkv_a_b   = (const float*)d_in[8];
    const float* kv_norm_w = (const float*)d_in[9];
    const float* wkv_b_w   = (const float*)d_in[10];
    const float* wo_w      = (const float*)d_in[11];
    const float* wo_b      = (const float*)d_in[12];
    float* out = (float*)d_out;

    float *hrnd, *projcat, *qlat, *kvn, *qkv, *vv, *wc, *biasc, *worn, *wkvbv, *wcat, *bcat;
    cudaGetSymbolAddress((void**)&hrnd,  g_hrnd);
    cudaGetSymbolAddress((void**)&projcat, g_projcat);
    cudaGetSymbolAddress((void**)&qlat,  g_qlat);
    cudaGetSymbolAddress((void**)&kvn,   g_kvn);
    cudaGetSymbolAddress((void**)&qkv,   g_qkv);
    cudaGetSymbolAddress((void**)&vv,    g_v);
    cudaGetSymbolAddress((void**)&wc,    g_wc);
    cudaGetSymbolAddress((void**)&biasc, g_biasc);
    cudaGetSymbolAddress((void**)&worn,  g_worn);
    cudaGetSymbolAddress((void**)&wkvbv, g_wkvbv);
    cudaGetSymbolAddress((void**)&wcat,  g_wcat);
    cudaGetSymbolAddress((void**)&bcat,  g_bcat);

    const int gsm128 = 3*(128+128)*36*4;                   // 110592
    const int asm_   = (2*64*132 + 128*68 + 256)*4;        // 103424
    cudaFuncSetAttribute((tgemm3<128,true,true>),   cudaFuncAttributeMaxDynamicSharedMemorySize, gsm128);
    cudaFuncSetAttribute((tgemm3<128,false,true>),  cudaFuncAttributeMaxDynamicSharedMemorySize, gsm128);
    cudaFuncSetAttribute(attn_tc, cudaFuncAttributeMaxDynamicSharedMemorySize, asm_);

    round_copy<<<NTOK*DIM/1024, 256>>>(h_ptr, hrnd);
    round_copy<<<DIM*NH*NDV/1024, 256>>>(wo_w, worn);
    prep_wkvbv<<<NH*NDV*DLKV/256, 256>>>(wkv_b_w, wkvbv);
    prep_wcat<<<384, 256>>>(wq_a_w, wq_a_b, wkv_a_w, wkv_a_b, wcat, bcat);
    prep_wc_kernel<<<NH*DLKV, DLQ>>>(wq_b_w, wq_b_b, wkv_b_w, wc, biasc);

    // merged latent projections: [8192,1024] x [384,1024]^T
    tgemm3<128,false,true><<<dim3(3, NTOK/128, 1), 256, gsm128>>>(
        hrnd, DIM, 0, wcat, DIM, 0, bcat, projcat, 384, 0, DIM);
    rms_kernel<<<NTOK, 128>>>(projcat, 384, 0,   q_norm_w,  qlat, DLQ);
    rms_kernel<<<NTOK, 128>>>(projcat, 384, 256, kv_norm_w, kvn,  DLKV);

    // absorbed q -> latent-kv: [8192,256] x [2048,256]^T (rounded for attention)
    tgemm3<128,true,true><<<dim3(16, NTOK/128, 1), 256, gsm128>>>(
        qlat, DLQ, 0, wc, DLQ, 0, biasc, qkv, NH*DLKV, 0, DLQ);

    // attention + fused per-head value projection
    attn_tc<<<dim3(SQ/128, NH, BB), 256, asm_>>>(qkv, kvn, wkvbv, vv);

    // out = v @ wo_w^T + wo_b: [8192,1024] x [1024,1024]^T
    tgemm3<128,false,true><<<dim3(8, NTOK/128, 1), 256, gsm128>>>(
        vv, NH*NDV, 0, worn, NH*NDV, 0, wo_b, out, DIM, 0, NH*NDV);
}

// round 11
// speedup vs baseline: 1.1238x; 1.1238x over previous
#include <cuda_runtime.h>
#include <cstdint>

#define SQ   2048
#define BB   4
#define DIM  1024
#define NH   16
#define NDQK 20
#define NDV  64
#define DLQ  256
#define DLKV 128
#define NTOK (BB*SQ)

__device__ float g_hrnd[(size_t)NTOK*DIM];
__device__ float g_projcat[(size_t)NTOK*384];
__device__ float g_qlat[NTOK*DLQ];
__device__ float g_kvn [NTOK*DLKV];
__device__ float g_qkv [(size_t)NTOK*NH*DLKV];
__device__ float g_v   [(size_t)NTOK*NH*NDV];
__device__ float g_wc  [NH*DLKV*DLQ];
__device__ float g_biasc[NH*DLKV];
__device__ float g_worn[DIM*NH*NDV];
__device__ float g_wkvbv[NH*NDV*DLKV];
__device__ float g_wcat[384*DIM];
__device__ float g_bcat[384];

// ======================= helpers =======================
__device__ __forceinline__ uint32_t f2tf(float f){
    uint32_t u; asm("cvt.rna.tf32.f32 %0, %1;" : "=r"(u) : "f"(f)); return u;
}
__device__ __forceinline__ float rnd(float f){ return __uint_as_float(f2tf(f)); }
__device__ __forceinline__ void mma8(float&c0,float&c1,float&c2,float&c3,
    uint32_t a0,uint32_t a1,uint32_t a2,uint32_t a3,uint32_t b0,uint32_t b1){
    asm volatile("mma.sync.aligned.m16n8k8.row.col.f32.tf32.tf32.f32 "
        "{%0,%1,%2,%3}, {%4,%5,%6,%7}, {%8,%9}, {%0,%1,%2,%3};"
        : "+f"(c0),"+f"(c1),"+f"(c2),"+f"(c3)
        : "r"(a0),"r"(a1),"r"(a2),"r"(a3),"r"(b0),"r"(b1));
}
__device__ __forceinline__ void ldsm4(uint32_t&r0,uint32_t&r1,uint32_t&r2,uint32_t&r3,uint32_t a){
    asm volatile("ldmatrix.sync.aligned.m8n8.x4.shared.b16 {%0,%1,%2,%3}, [%4];"
        : "=r"(r0),"=r"(r1),"=r"(r2),"=r"(r3) : "r"(a));
}
__device__ __forceinline__ uint32_t smem_u32(const void* p){
    uint32_t a;
    asm("{ .reg .u64 t; cvta.to.shared.u64 t, %1; cvt.u32.u64 %0, t; }" : "=r"(a) : "l"(p));
    return a;
}
__device__ __forceinline__ void cp16(uint32_t dst, const void* src){
    asm volatile("cp.async.cg.shared.global [%0], [%1], 16;" :: "r"(dst), "l"(src));
}
__device__ __forceinline__ void cp_commit(){ asm volatile("cp.async.commit_group;" ::: "memory"); }
template<int NW> __device__ __forceinline__ void cp_wait(){
    asm volatile("cp.async.wait_group %0;" :: "n"(NW) : "memory");
}
__device__ __forceinline__ uint32_t ldb(const float* p){ return __float_as_uint(*p); }

// ---------- prep ----------
__global__ void round_copy(const float* __restrict__ in, float* __restrict__ out){
    size_t i = ((size_t)blockIdx.x*256 + threadIdx.x)*4;
    float4 v = *(const float4*)&in[i];
    v.x=rnd(v.x); v.y=rnd(v.y); v.z=rnd(v.z); v.w=rnd(v.w);
    *(float4*)&out[i] = v;
}
__global__ void prep_wkvbv(const float* __restrict__ wkv_b_w, float* __restrict__ outp){
    int i = blockIdx.x*256 + threadIdx.x;          // over NH*64*128
    int h = i >> 13, rem = i & 8191;
    outp[i] = rnd(wkv_b_w[(size_t)(h*(NDQK+NDV) + NDQK)*DLKV + rem]);
}
__global__ void prep_wcat(const float* __restrict__ wq_a_w, const float* __restrict__ wq_a_b,
                          const float* __restrict__ wkv_a_w, const float* __restrict__ wkv_a_b,
                          float* __restrict__ wcat, float* __restrict__ bcat){
    int n = blockIdx.x;
    const float* src = (n < 256) ? (wq_a_w + (size_t)n*DIM) : (wkv_a_w + (size_t)(n-256)*DIM);
    for (int k = threadIdx.x; k < DIM; k += 256) wcat[(size_t)n*DIM + k] = rnd(src[k]);
    if (threadIdx.x == 0) bcat[n] = (n < 256) ? wq_a_b[n] : wkv_a_b[n-256];
}
__global__ void prep_wc_kernel(const float* __restrict__ wq_b_w,
                               const float* __restrict__ wq_b_b,
                               const float* __restrict__ wkv_b_w,
                               float* __restrict__ wc, float* __restrict__ biasc) {
    int hc = blockIdx.x, h = hc >> 7, c = hc & 127, l = threadIdx.x;
    float acc = 0.f, accb = 0.f;
    #pragma unroll
    for (int q = 0; q < NDQK; q++) {
        float kb = wkv_b_w[(size_t)(h*(NDQK+NDV) + q)*DLKV + c];
        acc  = fmaf(kb, wq_b_w[(size_t)(h*NDQK + q)*DLQ + l], acc);
        accb = fmaf(kb, wq_b_b[h*NDQK + q], accb);
    }
    wc[(size_t)hc*DLQ + l] = rnd(acc);
    if (l == 0) biasc[hc] = accb;
}

// ---------- merged RMSNorm (q: cols 0..255, kv: cols 256..383) ----------
__global__ void rms2_kernel(const float* __restrict__ in,
                            const float* __restrict__ wq, const float* __restrict__ wkv,
                            float* __restrict__ outq, float* __restrict__ outkv) {
    int row = blockIdx.x;
    const float* x = in + (size_t)row*384;
    float ssq = 0.f;
    for (int i = threadIdx.x; i < 256; i += 128) { float v = x[i]; ssq = fmaf(v, v, ssq); }
    float xk = x[256 + threadIdx.x];
    float ssk = xk*xk;
    #pragma unroll
    for (int d = 16; d; d >>= 1){
        ssq += __shfl_xor_sync(0xffffffffu, ssq, d);
        ssk += __shfl_xor_sync(0xffffffffu, ssk, d);
    }
    __shared__ float redq[4], redk[4];
    if ((threadIdx.x & 31) == 0){ redq[threadIdx.x>>5] = ssq; redk[threadIdx.x>>5] = ssk; }
    __syncthreads();
    float rq = rsqrtf((redq[0]+redq[1]+redq[2]+redq[3]) / 256.f + 1e-6f);
    float rk = rsqrtf((redk[0]+redk[1]+redk[2]+redk[3]) / 128.f + 1e-6f);
    for (int i = threadIdx.x; i < 256; i += 128)
        outq[(size_t)row*256 + i] = rnd(x[i] * rq * wq[i]);
    outkv[(size_t)row*128 + threadIdx.x] = rnd(xk * rk * wkv[threadIdx.x]);
}

// ---------- tf32 mma GEMM, cp.async 3-stage, ldmatrix, z-batched ----------
template<int BN, bool ROUND, bool BIAS>
__global__ __launch_bounds__(256, 2) void tgemm3(
    const float* __restrict__ A, int lda, size_t sAz,
    const float* __restrict__ Bm, int ldb, size_t sBz,
    const float* __restrict__ bias, float* __restrict__ C, int ldc, size_t sCz,
    int K)
{
    extern __shared__ float smem[];
    const int SSZ = (128+BN)*36;
    constexpr int NJ = BN/16;
    constexpr int NP = BN/32;

    const int mt = blockIdx.y*128, nt = blockIdx.x*BN;
    A  += (size_t)blockIdx.z*sAz;
    Bm += (size_t)blockIdx.z*sBz;
    C  += (size_t)blockIdx.z*sCz;

    const int tid = threadIdx.x, w = tid>>5, lane = tid&31;
    const int g = lane>>2, t = lane&3;
    const int wm = (w&3)*32, wn = (w>>2)*(BN/2);
    const int mat = lane>>3, r8 = lane&7;
    const int matr = mat&1, matc = mat>>1;

    const uint32_t smu = smem_u32(smem);
    const uint32_t aoff0 = (uint32_t)(((wm + matr*8 + r8)*36 + matc*4)*4);
    const uint32_t boff0 = (uint32_t)((128*36 + (wn + matc*8 + r8)*36 + matr*4)*4);

    float acc[2][NJ][4];
    #pragma unroll
    for (int i=0;i<2;i++)
        #pragma unroll
        for (int j=0;j<NJ;j++){ acc[i][j][0]=0.f; acc[i][j][1]=0.f; acc[i][j][2]=0.f; acc[i][j][3]=0.f; }

    const int NC = K >> 5;
    auto fetch = [&](int i, int slot){
        const int k0 = i << 5;
        float* dA = smem + slot*SSZ;
        float* dB = dA + 128*36;
        #pragma unroll
        for (int s2=0;s2<4;s2++){
            int v = tid + s2*256, r = v>>3, c4 = (v&7)<<2;
            cp16(smem_u32(&dA[r*36 + c4]), &A[(size_t)(mt+r)*lda + k0 + c4]);
        }
        #pragma unroll
        for (int s2=0;s2<BN/32;s2++){
            int v = tid + s2*256, r = v>>3, c4 = (v&7)<<2;
            cp16(smem_u32(&dB[r*36 + c4]), &Bm[(size_t)(nt+r)*ldb + k0 + c4]);
        }
        cp_commit();
    };
    fetch(0, 0);
    if (NC > 1) fetch(1, 1);

    for (int i=0;i<NC;i++){
        if (i == NC-1) cp_wait<0>(); else cp_wait<1>();
        __syncthreads();
        if (i+2 < NC) fetch(i+2, (i+2)%3);
        const uint32_t sb = smu + (uint32_t)((i%3)*SSZ*4);
        #pragma unroll
        for (int kk=0; kk<32; kk+=8){
            uint32_t af[2][4], bf[NJ][2];
            #pragma unroll
            for (int ii=0;ii<2;ii++)
                ldsm4(af[ii][0],af[ii][1],af[ii][2],af[ii][3],
                      sb + aoff0 + (uint32_t)(ii*16*36*4 + kk*4));
            #pragma unroll
            for (int p=0;p<NP;p++){
                uint32_t r0,r1,r2,r3;
                ldsm4(r0,r1,r2,r3, sb + boff0 + (uint32_t)(p*16*36*4 + kk*4));
                bf[2*p][0]=r0; bf[2*p][1]=r1; bf[2*p+1][0]=r2; bf[2*p+1][1]=r3;
            }
            #pragma unroll
            for (int ii=0;ii<2;ii++)
                #pragma unroll
                for (int j=0;j<NJ;j++)
                    mma8(acc[ii][j][0],acc[ii][j][1],acc[ii][j][2],acc[ii][j][3],
                         af[ii][0],af[ii][1],af[ii][2],af[ii][3],bf[j][0],bf[j][1]);
        }
    }
    #pragma unroll
    for (int ii=0;ii<2;ii++){
        int row0 = mt + wm + ii*16 + g, row1 = row0 + 8;
        #pragma unroll
        for (int j=0;j<NJ;j++){
            int col = nt + wn + j*8 + 2*t;
            float b0v = BIAS ? bias[col] : 0.f, b1v = BIAS ? bias[col+1] : 0.f;
            float o00 = acc[ii][j][0]+b0v, o01 = acc[ii][j][1]+b1v;
            float o10 = acc[ii][j][2]+b0v, o11 = acc[ii][j][3]+b1v;
            if (ROUND){ o00=rnd(o00); o01=rnd(o01); o10=rnd(o10); o11=rnd(o11); }
            *(float2*)&C[(size_t)row0*ldc + col] = make_float2(o00, o01);
            *(float2*)&C[(size_t)row1*ldc + col] = make_float2(o10, o11);
        }
    }
}

// ---------- flash attention (64-row tiles, 2 CTA/SM) + fused value projection ----------
__global__ __launch_bounds__(128, 2) void attn_tc(
    const float* __restrict__ qkv, const float* __restrict__ kvn,
    const float* __restrict__ wkvbv, float* __restrict__ vout)
{
    extern __shared__ float smf[];
    float*    sKV = smf;                          // [2][64][132]
    uint32_t* sP  = (uint32_t*)(smf + 2*64*132);  // [64][68] tf32 bits
    float*    sAl = smf + 2*64*132 + 64*68;       // [64] alpha
    float*    sL  = sAl + 64;                     // [64] sum

    const int qt = (int)gridDim.x - 1 - (int)blockIdx.x;
    const int h = blockIdx.y, b = blockIdx.z;
    const int tid = threadIdx.x, w = tid>>5, lane = tid & 31;
    const int g = lane >> 2, t = lane & 3;
    const int mat = lane>>3, r8 = lane&7;
    const int matr = mat&1, matc = mat>>1;
    const int q0 = qt*64;
    const int mrow = w*16 + g;
    const int wn = w*32;
    const float scale = 0.22360679774997896f;

    const uint32_t kvu = smem_u32(sKV);
    const uint32_t pu  = smem_u32(sP);
    const uint32_t koff0 = (uint32_t)(((matc*8 + r8)*132 + matr*4)*4);
    const uint32_t poff0 = (uint32_t)(((matr*8 + r8)*68 + matc*4)*4);

    {
        #pragma unroll
        for (int s2=0;s2<16;s2++){
            int v = tid + s2*128, r = v>>5, c4 = (v&31)<<2;
            cp16(smem_u32(&sKV[r*132 + c4]), &kvn[((size_t)(b*SQ + r))*128 + c4]);
        }
        cp_commit();
    }
    uint32_t qf[16][4];
    {
        const float* qb = &qkv[((size_t)((b*SQ + q0)*NH + h))*128];
        const size_t rs = (size_t)NH*128;
        #pragma unroll
        for (int kk = 0; kk < 16; kk++) {
            qf[kk][0] = ldb(qb + (size_t)(mrow  )*rs + kk*8 + t);
            qf[kk][1] = ldb(qb + (size_t)(mrow+8)*rs + kk*8 + t);
            qf[kk][2] = ldb(qb + (size_t)(mrow  )*rs + kk*8 + t + 4);
            qf[kk][3] = ldb(qb + (size_t)(mrow+8)*rs + kk*8 + t + 4);
        }
    }

    float o[4][4][4];
    #pragma unroll
    for (int mi=0;mi<4;mi++)
        #pragma unroll
        for (int j=0;j<4;j++){ o[mi][j][0]=0.f; o[mi][j][1]=0.f; o[mi][j][2]=0.f; o[mi][j][3]=0.f; }
    float m0=-1e30f, m1=-1e30f, l0=0.f, l1=0.f;

    for (int kt = 0; kt <= qt; kt++) {
        const int st = kt & 1;
        __syncthreads();
        {   // prefetch next KV tile, or the value-projection weight W on the last tile
            float* dst = sKV + (1-st)*64*132;
            const float* src = (kt < qt)
                ? &kvn[((size_t)(b*SQ + (kt+1)*64))*128]
                : &wkvbv[(size_t)h*NDV*DLKV];
            #pragma unroll
            for (int s2=0;s2<16;s2++){
                int v = tid + s2*128, r = v>>5, c4 = (v&31)<<2;
                cp16(smem_u32(&dst[r*132 + c4]), src + (size_t)r*128 + c4);
            }
            cp_commit();
            cp_wait<1>();        // current tile resident; newest fetch may stay in flight
        }
        __syncthreads();
        const float* cKV = sKV + st*64*132;
        const uint32_t kB = kvu + (uint32_t)(st*64*132*4);
        const int k0 = kt*64;

        float s[8][4];
        #pragma unroll
        for (int j = 0; j < 8; j++) { s[j][0]=0.f; s[j][1]=0.f; s[j][2]=0.f; s[j][3]=0.f; }
        #pragma unroll
        for (int kk = 0; kk < 16; kk++) {
            uint32_t bf[8][2];
            #pragma unroll
            for (int p=0;p<4;p++){
                uint32_t r0,r1,r2,r3;
                ldsm4(r0,r1,r2,r3, kB + koff0 + (uint32_t)(p*16*132*4 + kk*8*4));
                bf[2*p][0]=r0; bf[2*p][1]=r1; bf[2*p+1][0]=r2; bf[2*p+1][1]=r3;
            }
            #pragma unroll
            for (int j = 0; j < 8; j++)
                mma8(s[j][0],s[j][1],s[j][2],s[j][3], qf[kk][0],qf[kk][1],qf[kk][2],qf[kk][3],
                     bf[j][0],bf[j][1]);
        }

        const bool diag = (kt == qt);
        const int grow0 = q0 + mrow, grow1 = grow0 + 8;
        float mx0=-1e30f, mx1=-1e30f;
        #pragma unroll
        for (int j = 0; j < 8; j++) {
            int c = k0 + j*8 + 2*t;
            #pragma unroll
            for (int e = 0; e < 2; e++) {
                float v0 = s[j][e]*scale, v1 = s[j][2+e]*scale;
                if (diag && (c+e) > grow0) v0 = -1e30f;
                if (diag && (c+e) > grow1) v1 = -1e30f;
                s[j][e] = v0; s[j][2+e] = v1;
                mx0 = fmaxf(mx0, v0); mx1 = fmaxf(mx1, v1);
            }
        }
        mx0 = fmaxf(mx0, __shfl_xor_sync(0xffffffffu, mx0, 1));
        mx0 = fmaxf(mx0, __shfl_xor_sync(0xffffffffu, mx0, 2));
        mx1 = fmaxf(mx1, __shfl_xor_sync(0xffffffffu, mx1, 1));
        mx1 = fmaxf(mx1, __shfl_xor_sync(0xffffffffu, mx1, 2));
        float nm0 = fmaxf(m0, mx0), nm1 = fmaxf(m1, mx1);
        float al0 = __expf(m0 - nm0), al1 = __expf(m1 - nm1);
        m0 = nm0; m1 = nm1;
        float ls0 = 0.f, ls1 = 0.f;
        #pragma unroll
        for (int j = 0; j < 8; j++) {
            float p00 = __expf(s[j][0]-nm0), p01 = __expf(s[j][1]-nm0);
            float p10 = __expf(s[j][2]-nm1), p11 = __expf(s[j][3]-nm1);
            ls0 += p00 + p01; ls1 += p10 + p11;
            int c = j*8 + 2*t;
            sP[(mrow  )*68 + c] = f2tf(p00); sP[(mrow  )*68 + c+1] = f2tf(p01);
            sP[(mrow+8)*68 + c] = f2tf(p10); sP[(mrow+8)*68 + c+1] = f2tf(p11);
        }
        ls0 += __shfl_xor_sync(0xffffffffu, ls0, 1);
        ls0 += __shfl_xor_sync(0xffffffffu, ls0, 2);
        ls1 += __shfl_xor_sync(0xffffffffu, ls1, 1);
        ls1 += __shfl_xor_sync(0xffffffffu, ls1, 2);
        l0 = l0*al0 + ls0; l1 = l1*al1 + ls1;
        if (t == 0){ sAl[mrow] = al0; sAl[mrow+8] = al1; }
        __syncthreads();

        float alo[4], ahi[4];
        #pragma unroll
        for (int mi=0;mi<4;mi++){ alo[mi]=sAl[mi*16+g]; ahi[mi]=sAl[mi*16+8+g]; }
        #pragma unroll
        for (int mi=0;mi<4;mi++)
            #pragma unroll
            for (int j=0;j<4;j++){
                o[mi][j][0]*=alo[mi]; o[mi][j][1]*=alo[mi];
                o[mi][j][2]*=ahi[mi]; o[mi][j][3]*=ahi[mi];
            }
        #pragma unroll
        for (int kb = 0; kb < 64; kb += 8) {
            uint32_t pf[4][4];
            #pragma unroll
            for (int mi=0;mi<4;mi++)
                ldsm4(pf[mi][0],pf[mi][1],pf[mi][2],pf[mi][3],
                      pu + poff0 + (uint32_t)(mi*16*68*4 + kb*4));
            #pragma unroll
            for (int j=0;j<4;j++){
                uint32_t b0 = ldb(&cKV[(kb+t  )*132 + wn + j*8 + g]);
                uint32_t b1 = ldb(&cKV[(kb+t+4)*132 + wn + j*8 + g]);
                #pragma unroll
                for (int mi=0;mi<4;mi++)
                    mma8(o[mi][j][0],o[mi][j][1],o[mi][j][2],o[mi][j][3],
                         pf[mi][0],pf[mi][1],pf[mi][2],pf[mi][3], b0,b1);
            }
        }
    }

    // ---------- fused value projection: v = O_norm @ W^T ----------
    if (t == 0){ sL[mrow] = l0; sL[mrow+8] = l1; }
    __syncthreads();                        // PV reads done, sL visible
    cp_wait<0>();                           // W resident in buffer (1-stO)
    const int stO = qt & 1;
    float* sO = sKV + stO*64*132;
    const uint32_t oB = kvu + (uint32_t)(stO*64*132*4);
    const uint32_t wB = kvu + (uint32_t)((1-stO)*64*132*4);

    // stage normalized, rounded O (warp owns cols [wn, wn+32) for all rows)
    #pragma unroll
    for (int mi=0;mi<4;mi++){
        int lr0 = mi*16 + g, lr1 = lr0 + 8;
        float inv0 = 1.f/sL[lr0], inv1 = 1.f/sL[lr1];
        #pragma unroll
        for (int j=0;j<4;j++){
            int col = wn + j*8 + 2*t;
            *(float2*)&sO[lr0*132 + col] = make_float2(rnd(o[mi][j][0]*inv0), rnd(o[mi][j][1]*inv0));
            *(float2*)&sO[lr1*132 + col] = make_float2(rnd(o[mi][j][2]*inv1), rnd(o[mi][j][3]*inv1));
        }
    }
    __syncthreads();

    // vproj: warp w computes rows [w*16, w*16+16) x all 64 cols, k = 128
    {
        const int rw = w*16;
        const uint32_t aoffO = (uint32_t)(((rw + matr*8 + r8)*132 + matc*4)*4);
        float vo[8][4];
        #pragma unroll
        for (int j=0;j<8;j++){ vo[j][0]=0.f; vo[j][1]=0.f; vo[j][2]=0.f; vo[j][3]=0.f; }
        #pragma unroll
        for (int kk=0; kk<16; kk++){
            uint32_t a0,a1,a2,a3;
            ldsm4(a0,a1,a2,a3, oB + aoffO + (uint32_t)(kk*8*4));
            uint32_t wf[8][2];
            #pragma unroll
            for (int p=0;p<4;p++){
                uint32_t r0,r1,r2,r3;
                ldsm4(r0,r1,r2,r3, wB + koff0 + (uint32_t)(p*16*132*4 + kk*8*4));
                wf[2*p][0]=r0; wf[2*p][1]=r1; wf[2*p+1][0]=r2; wf[2*p+1][1]=r3;
            }
            #pragma unroll
            for (int j=0;j<8;j++)
                mma8(vo[j][0],vo[j][1],vo[j][2],vo[j][3], a0,a1,a2,a3, wf[j][0],wf[j][1]);
        }
        int grow = q0 + rw + g;
        #pragma unroll
        for (int j=0;j<8;j++){
            int col = h*NDV + j*8 + 2*t;
            size_t base0 = (size_t)(b*SQ + grow    )*(NH*NDV) + col;
            size_t base1 = (size_t)(b*SQ + grow + 8)*(NH*NDV) + col;
            *(float2*)&vout[base0] = make_float2(rnd(vo[j][0]), rnd(vo[j][1]));
            *(float2*)&vout[base1] = make_float2(rnd(vo[j][2]), rnd(vo[j][3]));
        }
    }
}

// ---------- launch ----------
extern "C" void kernel_launch(void* const* d_in, const int* in_sizes, int n_in,
                              void* d_out, int out_size)
{
    const float* h_ptr     = (const float*)d_in[0];
    const float* wq_a_w    = (const float*)d_in[2];
    const float* wq_a_b    = (const float*)d_in[3];
    const float* q_norm_w  = (const float*)d_in[4];
    const float* wq_b_w    = (const float*)d_in[5];
    const float* wq_b_b    = (const float*)d_in[6];
    const float* wkv_a_w   = (const float*)d_in[7];
    const float* wkv_a_b   = (const float*)d_in[8];
    const float* kv_norm_w = (const float*)d_in[9];
    const float* wkv_b_w   = (const float*)d_in[10];
    const float* wo_w      = (const float*)d_in[11];
    const float* wo_b      = (const float*)d_in[12];
    float* out = (float*)d_out;

    float *hrnd, *projcat, *qlat, *kvn, *qkv, *vv, *wc, *biasc, *worn, *wkvbv, *wcat, *bcat;
    cudaGetSymbolAddress((void**)&hrnd,  g_hrnd);
    cudaGetSymbolAddress((void**)&projcat, g_projcat);
    cudaGetSymbolAddress((void**)&qlat,  g_qlat);
    cudaGetSymbolAddress((void**)&kvn,   g_kvn);
    cudaGetSymbolAddress((void**)&qkv,   g_qkv);
    cudaGetSymbolAddress((void**)&vv,    g_v);
    cudaGetSymbolAddress((void**)&wc,    g_wc);
    cudaGetSymbolAddress((void**)&biasc, g_biasc);
    cudaGetSymbolAddress((void**)&worn,  g_worn);
    cudaGetSymbolAddress((void**)&wkvbv, g_wkvbv);
    cudaGetSymbolAddress((void**)&wcat,  g_wcat);
    cudaGetSymbolAddress((void**)&bcat,  g_bcat);

    const int gsm128 = 3*(128+128)*36*4;                   // 110592
    const int asm_   = (2*64*132 + 64*68 + 128)*4;         // 85504
    cudaFuncSetAttribute((tgemm3<128,true,true>),   cudaFuncAttributeMaxDynamicSharedMemorySize, gsm128);
    cudaFuncSetAttribute((tgemm3<128,false,true>),  cudaFuncAttributeMaxDynamicSharedMemorySize, gsm128);
    cudaFuncSetAttribute(attn_tc, cudaFuncAttributeMaxDynamicSharedMemorySize, asm_);

    round_copy<<<NTOK*DIM/1024, 256>>>(h_ptr, hrnd);
    round_copy<<<DIM*NH*NDV/1024, 256>>>(wo_w, worn);
    prep_wkvbv<<<NH*NDV*DLKV/256, 256>>>(wkv_b_w, wkvbv);
    prep_wcat<<<384, 256>>>(wq_a_w, wq_a_b, wkv_a_w, wkv_a_b, wcat, bcat);
    prep_wc_kernel<<<NH*DLKV, DLQ>>>(wq_b_w, wq_b_b, wkv_b_w, wc, biasc);

    // merged latent projections: [8192,1024] x [384,1024]^T
    tgemm3<128,false,true><<<dim3(3, NTOK/128, 1), 256, gsm128>>>(
        hrnd, DIM, 0, wcat, DIM, 0, bcat, projcat, 384, 0, DIM);
    rms2_kernel<<<NTOK, 128>>>(projcat, q_norm_w, kv_norm_w, qlat, kvn);

    // absorbed q -> latent-kv: [8192,256] x [2048,256]^T (rounded for attention)
    tgemm3<128,true,true><<<dim3(16, NTOK/128, 1), 256, gsm128>>>(
        qlat, DLQ, 0, wc, DLQ, 0, biasc, qkv, NH*DLKV, 0, DLQ);

    // attention + fused per-head value projection
    attn_tc<<<dim3(SQ/64, NH, BB), 128, asm_>>>(qkv, kvn, wkvbv, vv);

    // out = v @ wo_w^T + wo_b: [8192,1024] x [1024,1024]^T
    tgemm3<128,false,true><<<dim3(8, NTOK/128, 1), 256, gsm128>>>(
        vv, NH*NDV, 0, worn, NH*NDV, 0, wo_b, out, DIM, 0, NH*NDV);
}

// round 13
// speedup vs baseline: 1.1502x; 1.0235x over previous
#include <cuda_runtime.h>
#include <cstdint>

#define SQ   2048
#define BB   4
#define DIM  1024
#define NH   16
#define NDQK 20
#define NDV  64
#define DLQ  256
#define DLKV 128
#define NTOK (BB*SQ)

__device__ float g_projcat[(size_t)NTOK*384];
__device__ float g_qlat[NTOK*DLQ];
__device__ float g_kvn [NTOK*DLKV];
__device__ float g_qkv [(size_t)NTOK*NH*DLKV];
__device__ float g_v   [(size_t)NTOK*NH*NDV];
__device__ float g_wc  [NH*DLKV*DLQ];
__device__ float g_biasc[NH*DLKV];
__device__ float g_worn[DIM*NH*NDV];
__device__ float g_wkvbv[NH*NDV*DLKV];
__device__ float g_wcat[384*DIM];
__device__ float g_bcat[384];

// ======================= helpers =======================
__device__ __forceinline__ uint32_t f2tf(float f){
    uint32_t u; asm("cvt.rna.tf32.f32 %0, %1;" : "=r"(u) : "f"(f)); return u;
}
__device__ __forceinline__ float rnd(float f){ return __uint_as_float(f2tf(f)); }
__device__ __forceinline__ void mma8(float&c0,float&c1,float&c2,float&c3,
    uint32_t a0,uint32_t a1,uint32_t a2,uint32_t a3,uint32_t b0,uint32_t b1){
    asm volatile("mma.sync.aligned.m16n8k8.row.col.f32.tf32.tf32.f32 "
        "{%0,%1,%2,%3}, {%4,%5,%6,%7}, {%8,%9}, {%0,%1,%2,%3};"
        : "+f"(c0),"+f"(c1),"+f"(c2),"+f"(c3)
        : "r"(a0),"r"(a1),"r"(a2),"r"(a3),"r"(b0),"r"(b1));
}
__device__ __forceinline__ void ldsm4(uint32_t&r0,uint32_t&r1,uint32_t&r2,uint32_t&r3,uint32_t a){
    asm volatile("ldmatrix.sync.aligned.m8n8.x4.shared.b16 {%0,%1,%2,%3}, [%4];"
        : "=r"(r0),"=r"(r1),"=r"(r2),"=r"(r3) : "r"(a));
}
__device__ __forceinline__ uint32_t smem_u32(const void* p){
    uint32_t a;
    asm("{ .reg .u64 t; cvta.to.shared.u64 t, %1; cvt.u32.u64 %0, t; }" : "=r"(a) : "l"(p));
    return a;
}
__device__ __forceinline__ void cp16(uint32_t dst, const void* src){
    asm volatile("cp.async.cg.shared.global [%0], [%1], 16;" :: "r"(dst), "l"(src));
}
__device__ __forceinline__ void cp_commit(){ asm volatile("cp.async.commit_group;" ::: "memory"); }
template<int NW> __device__ __forceinline__ void cp_wait(){
    asm volatile("cp.async.wait_group %0;" :: "n"(NW) : "memory");
}
__device__ __forceinline__ uint32_t ldb(const float* p){ return __float_as_uint(*p); }

// ---------- merged weight prep ----------
// grid 1536: [0,1024) worn (float4), [1024,1152) wkvbv (float4), [1152,1536) wcat
__global__ void prep_weights(const float* __restrict__ wo_w, const float* __restrict__ wkv_b_w,
                             const float* __restrict__ wq_a_w, const float* __restrict__ wq_a_b,
                             const float* __restrict__ wkv_a_w, const float* __restrict__ wkv_a_b,
                             float* __restrict__ worn, float* __restrict__ wkvbv,
                             float* __restrict__ wcat, float* __restrict__ bcat){
    int bx = blockIdx.x;
    if (bx < 1024){                        // worn: round wo_w (1M elems)
        size_t i = ((size_t)bx*256 + threadIdx.x)*4;
        float4 v = *(const float4*)&wo_w[i];
        v.x=rnd(v.x); v.y=rnd(v.y); v.z=rnd(v.z); v.w=rnd(v.w);
        *(float4*)&worn[i] = v;
    } else if (bx < 1152){                 // wkvbv: per-head value slice (131072 elems)
        int i = (bx-1024)*1024 + threadIdx.x*4;
        int h = i >> 13, rem = i & 8191;
        float4 v = *(const float4*)&wkv_b_w[(size_t)(h*(NDQK+NDV) + NDQK)*DLKV + rem];
        v.x=rnd(v.x); v.y=rnd(v.y); v.z=rnd(v.z); v.w=rnd(v.w);
        *(float4*)&wkvbv[i] = v;
    } else {                               // wcat + bcat
        int n = bx - 1152;
        const float* src = (n < 256) ? (wq_a_w + (size_t)n*DIM) : (wkv_a_w + (size_t)(n-256)*DIM);
        for (int k = threadIdx.x; k < DIM; k += 256) wcat[(size_t)n*DIM + k] = rnd(src[k]);
        if (threadIdx.x == 0) bcat[n] = (n < 256) ? wq_a_b[n] : wkv_a_b[n-256];
    }
}
__global__ void prep_wc_kernel(const float* __restrict__ wq_b_w,
                               const float* __restrict__ wq_b_b,
                               const float* __restrict__ wkv_b_w,
                               float* __restrict__ wc, float* __restrict__ biasc) {
    int hc = blockIdx.x, h = hc >> 7, c = hc & 127, l = threadIdx.x;
    float acc = 0.f, accb = 0.f;
    #pragma unroll
    for (int q = 0; q < NDQK; q++) {
        float kb = wkv_b_w[(size_t)(h*(NDQK+NDV) + q)*DLKV + c];
        acc  = fmaf(kb, wq_b_w[(size_t)(h*NDQK + q)*DLQ + l], acc);
        accb = fmaf(kb, wq_b_b[h*NDQK + q], accb);
    }
    wc[(size_t)hc*DLQ + l] = rnd(acc);
    if (l == 0) biasc[hc] = accb;
}

// ---------- merged RMSNorm ----------
__global__ void rms2_kernel(const float* __restrict__ in,
                            const float* __restrict__ wq, const float* __restrict__ wkv,
                            float* __restrict__ outq, float* __restrict__ outkv) {
    int row = blockIdx.x;
    const float* x = in + (size_t)row*384;
    float ssq = 0.f;
    for (int i = threadIdx.x; i < 256; i += 128) { float v = x[i]; ssq = fmaf(v, v, ssq); }
    float xk = x[256 + threadIdx.x];
    float ssk = xk*xk;
    #pragma unroll
    for (int d = 16; d; d >>= 1){
        ssq += __shfl_xor_sync(0xffffffffu, ssq, d);
        ssk += __shfl_xor_sync(0xffffffffu, ssk, d);
    }
    __shared__ float redq[4], redk[4];
    if ((threadIdx.x & 31) == 0){ redq[threadIdx.x>>5] = ssq; redk[threadIdx.x>>5] = ssk; }
    __syncthreads();
    float rq = rsqrtf((redq[0]+redq[1]+redq[2]+redq[3]) / 256.f + 1e-6f);
    float rk = rsqrtf((redk[0]+redk[1]+redk[2]+redk[3]) / 128.f + 1e-6f);
    for (int i = threadIdx.x; i < 256; i += 128)
        outq[(size_t)row*256 + i] = rnd(x[i] * rq * wq[i]);
    outkv[(size_t)row*128 + threadIdx.x] = rnd(xk * rk * wkv[threadIdx.x]);
}

// ---------- tf32 mma GEMM, cp.async 3-stage, ldmatrix, z-batched ----------
template<int BN, bool ROUND, bool BIAS, bool CVTA>
__global__ __launch_bounds__(256, 2) void tgemm3(
    const float* __restrict__ A, int lda, size_t sAz,
    const float* __restrict__ Bm, int ldb, size_t sBz,
    const float* __restrict__ bias, float* __restrict__ C, int ldc, size_t sCz,
    int K)
{
    extern __shared__ float smem[];
    const int SSZ = (128+BN)*36;
    constexpr int NJ = BN/16;
    constexpr int NP = BN/32;

    const int mt = blockIdx.y*128, nt = blockIdx.x*BN;
    A  += (size_t)blockIdx.z*sAz;
    Bm += (size_t)blockIdx.z*sBz;
    C  += (size_t)blockIdx.z*sCz;

    const int tid = threadIdx.x, w = tid>>5, lane = tid&31;
    const int g = lane>>2, t = lane&3;
    const int wm = (w&3)*32, wn = (w>>2)*(BN/2);
    const int mat = lane>>3, r8 = lane&7;
    const int matr = mat&1, matc = mat>>1;

    const uint32_t smu = smem_u32(smem);
    const uint32_t aoff0 = (uint32_t)(((wm + matr*8 + r8)*36 + matc*4)*4);
    const uint32_t boff0 = (uint32_t)((128*36 + (wn + matc*8 + r8)*36 + matr*4)*4);

    float acc[2][NJ][4];
    #pragma unroll
    for (int i=0;i<2;i++)
        #pragma unroll
        for (int j=0;j<NJ;j++){ acc[i][j][0]=0.f; acc[i][j][1]=0.f; acc[i][j][2]=0.f; acc[i][j][3]=0.f; }

    const int NC = K >> 5;
    auto fetch = [&](int i, int slot){
        const int k0 = i << 5;
        float* dA = smem + slot*SSZ;
        float* dB = dA + 128*36;
        #pragma unroll
        for (int s2=0;s2<4;s2++){
            int v = tid + s2*256, r = v>>3, c4 = (v&7)<<2;
            cp16(smem_u32(&dA[r*36 + c4]), &A[(size_t)(mt+r)*lda + k0 + c4]);
        }
        #pragma unroll
        for (int s2=0;s2<BN/32;s2++){
            int v = tid + s2*256, r = v>>3, c4 = (v&7)<<2;
            cp16(smem_u32(&dB[r*36 + c4]), &Bm[(size_t)(nt+r)*ldb + k0 + c4]);
        }
        cp_commit();
    };
    fetch(0, 0);
    if (NC > 1) fetch(1, 1);

    for (int i=0;i<NC;i++){
        if (i == NC-1) cp_wait<0>(); else cp_wait<1>();
        __syncthreads();
        if (i+2 < NC) fetch(i+2, (i+2)%3);
        const uint32_t sb = smu + (uint32_t)((i%3)*SSZ*4);
        #pragma unroll
        for (int kk=0; kk<32; kk+=8){
            uint32_t af[2][4], bf[NJ][2];
            #pragma unroll
            for (int ii=0;ii<2;ii++){
                ldsm4(af[ii][0],af[ii][1],af[ii][2],af[ii][3],
                      sb + aoff0 + (uint32_t)(ii*16*36*4 + kk*4));
                if (CVTA){
                    af[ii][0]=f2tf(__uint_as_float(af[ii][0]));
                    af[ii][1]=f2tf(__uint_as_float(af[ii][1]));
                    af[ii][2]=f2tf(__uint_as_float(af[ii][2]));
                    af[ii][3]=f2tf(__uint_as_float(af[ii][3]));
                }
            }
            #pragma unroll
            for (int p=0;p<NP;p++){
                uint32_t r0,r1,r2,r3;
                ldsm4(r0,r1,r2,r3, sb + boff0 + (uint32_t)(p*16*36*4 + kk*4));
                bf[2*p][0]=r0; bf[2*p][1]=r1; bf[2*p+1][0]=r2; bf[2*p+1][1]=r3;
            }
            #pragma unroll
            for (int ii=0;ii<2;ii++)
                #pragma unroll
                for (int j=0;j<NJ;j++)
                    mma8(acc[ii][j][0],acc[ii][j][1],acc[ii][j][2],acc[ii][j][3],
                         af[ii][0],af[ii][1],af[ii][2],af[ii][3],bf[j][0],bf[j][1]);
        }
    }
    #pragma unroll
    for (int ii=0;ii<2;ii++){
        int row0 = mt + wm + ii*16 + g, row1 = row0 + 8;
        #pragma unroll
        for (int j=0;j<NJ;j++){
            int col = nt + wn + j*8 + 2*t;
            float b0v = BIAS ? bias[col] : 0.f, b1v = BIAS ? bias[col+1] : 0.f;
            float o00 = acc[ii][j][0]+b0v, o01 = acc[ii][j][1]+b1v;
            float o10 = acc[ii][j][2]+b0v, o11 = acc[ii][j][3]+b1v;
            if (ROUND){ o00=rnd(o00); o01=rnd(o01); o10=rnd(o10); o11=rnd(o11); }
            *(float2*)&C[(size_t)row0*ldc + col] = make_float2(o00, o01);
            *(float2*)&C[(size_t)row1*ldc + col] = make_float2(o10, o11);
        }
    }
}

// ---------- flash attention (64-row tiles, 2 CTA/SM) + fused value projection ----------
__global__ __launch_bounds__(128, 2) void attn_tc(
    const float* __restrict__ qkv, const float* __restrict__ kvn,
    const float* __restrict__ wkvbv, float* __restrict__ vout)
{
    extern __shared__ float smf[];
    float*    sKV = smf;                          // [2][64][132]
    uint32_t* sP  = (uint32_t*)(smf + 2*64*132);  // [64][68] tf32 bits
    float*    sAl = smf + 2*64*132 + 64*68;       // [64] alpha
    float*    sL  = sAl + 64;                     // [64] sum

    const int qt = (int)gridDim.x - 1 - (int)blockIdx.x;
    const int h = blockIdx.y, b = blockIdx.z;
    const int tid = threadIdx.x, w = tid>>5, lane = tid & 31;
    const int g = lane >> 2, t = lane & 3;
    const int mat = lane>>3, r8 = lane&7;
    const int matr = mat&1, matc = mat>>1;
    const int q0 = qt*64;
    const int mrow = w*16 + g;
    const int wn = w*32;
    const float scale = 0.22360679774997896f;

    const uint32_t kvu = smem_u32(sKV);
    const uint32_t pu  = smem_u32(sP);
    const uint32_t koff0 = (uint32_t)(((matc*8 + r8)*132 + matr*4)*4);
    const uint32_t poff0 = (uint32_t)(((matr*8 + r8)*68 + matc*4)*4);

    // prefetch KV tile 0 -> buffer 0
    {
        #pragma unroll
        for (int s2=0;s2<16;s2++){
            int v = tid + s2*128, r = v>>5, c4 = (v&31)<<2;
            cp16(smem_u32(&sKV[r*132 + c4]), &kvn[((size_t)(b*SQ + r))*128 + c4]);
        }
        cp_commit();
    }
    // stage Q tile (coalesced) -> buffer 1, lift fragments via ldsm
    {
        float* dstQ = sKV + 64*132;
        const float* qb = &qkv[((size_t)((b*SQ + q0)*NH + h))*128];
        #pragma unroll
        for (int s2=0;s2<16;s2++){
            int v = tid + s2*128, r = v>>5, c4 = (v&31)<<2;
            cp16(smem_u32(&dstQ[r*132 + c4]), qb + (size_t)r*(NH*128) + c4);
        }
        cp_commit();
    }
    cp_wait<0>();
    __syncthreads();
    uint32_t qf[16][4];
    {
        const uint32_t qB = kvu + (uint32_t)(64*132*4);
        const uint32_t qoff = (uint32_t)(((w*16 + matr*8 + r8)*132 + matc*4)*4);
        #pragma unroll
        for (int kk=0; kk<16; kk++)
            ldsm4(qf[kk][0],qf[kk][1],qf[kk][2],qf[kk][3], qB + qoff + (uint32_t)(kk*8*4));
    }

    float o[4][4][4];
    #pragma unroll
    for (int mi=0;mi<4;mi++)
        #pragma unroll
        for (int j=0;j<4;j++){ o[mi][j][0]=0.f; o[mi][j][1]=0.f; o[mi][j][2]=0.f; o[mi][j][3]=0.f; }
    float m0=-1e30f, m1=-1e30f, l0=0.f, l1=0.f;

    for (int kt = 0; kt <= qt; kt++) {
        const int st = kt & 1;
        __syncthreads();
        {   // prefetch next KV tile, or the value-projection weight W on the last tile
            float* dst = sKV + (1-st)*64*132;
            const float* src = (kt < qt)
                ? &kvn[((size_t)(b*SQ + (kt+1)*64))*128]
                : &wkvbv[(size_t)h*NDV*DLKV];
            #pragma unroll
            for (int s2=0;s2<16;s2++){
                int v = tid + s2*128, r = v>>5, c4 = (v&31)<<2;
                cp16(smem_u32(&dst[r*132 + c4]), src + (size_t)r*128 + c4);
            }
            cp_commit();
            cp_wait<1>();
        }
        __syncthreads();
        const float* cKV = sKV + st*64*132;
        const uint32_t kB = kvu + (uint32_t)(st*64*132*4);
        const int k0 = kt*64;

        float s[8][4];
        #pragma unroll
        for (int j = 0; j < 8; j++) { s[j][0]=0.f; s[j][1]=0.f; s[j][2]=0.f; s[j][3]=0.f; }
        #pragma unroll
        for (int kk = 0; kk < 16; kk++) {
            uint32_t bf[8][2];
            #pragma unroll
            for (int p=0;p<4;p++){
                uint32_t r0,r1,r2,r3;
                ldsm4(r0,r1,r2,r3, kB + koff0 + (uint32_t)(p*16*132*4 + kk*8*4));
                bf[2*p][0]=r0; bf[2*p][1]=r1; bf[2*p+1][0]=r2; bf[2*p+1][1]=r3;
            }
            #pragma unroll
            for (int j = 0; j < 8; j++)
                mma8(s[j][0],s[j][1],s[j][2],s[j][3], qf[kk][0],qf[kk][1],qf[kk][2],qf[kk][3],
                     bf[j][0],bf[j][1]);
        }

        const bool diag = (kt == qt);
        const int grow0 = q0 + mrow, grow1 = grow0 + 8;
        float mx0=-1e30f, mx1=-1e30f;
        #pragma unroll
        for (int j = 0; j < 8; j++) {
            int c = k0 + j*8 + 2*t;
            #pragma unroll
            for (int e = 0; e < 2; e++) {
                float v0 = s[j][e]*scale, v1 = s[j][2+e]*scale;
                if (diag && (c+e) > grow0) v0 = -1e30f;
                if (diag && (c+e) > grow1) v1 = -1e30f;
                s[j][e] = v0; s[j][2+e] = v1;
                mx0 = fmaxf(mx0, v0); mx1 = fmaxf(mx1, v1);
            }
        }
        mx0 = fmaxf(mx0, __shfl_xor_sync(0xffffffffu, mx0, 1));
        mx0 = fmaxf(mx0, __shfl_xor_sync(0xffffffffu, mx0, 2));
        mx1 = fmaxf(mx1, __shfl_xor_sync(0xffffffffu, mx1, 1));
        mx1 = fmaxf(mx1, __shfl_xor_sync(0xffffffffu, mx1, 2));
        float nm0 = fmaxf(m0, mx0), nm1 = fmaxf(m1, mx1);
        float al0 = __expf(m0 - nm0), al1 = __expf(m1 - nm1);
        m0 = nm0; m1 = nm1;
        float ls0 = 0.f, ls1 = 0.f;
        #pragma unroll
        for (int j = 0; j < 8; j++) {
            float p00 = __expf(s[j][0]-nm0), p01 = __expf(s[j][1]-nm0);
            float p10 = __expf(s[j][2]-nm1), p11 = __expf(s[j][3]-nm1);
            ls0 += p00 + p01; ls1 += p10 + p11;
            int c = j*8 + 2*t;
            sP[(mrow  )*68 + c] = f2tf(p00); sP[(mrow  )*68 + c+1] = f2tf(p01);
            sP[(mrow+8)*68 + c] = f2tf(p10); sP[(mrow+8)*68 + c+1] = f2tf(p11);
        }
        ls0 += __shfl_xor_sync(0xffffffffu, ls0, 1);
        ls0 += __shfl_xor_sync(0xffffffffu, ls0, 2);
        ls1 += __shfl_xor_sync(0xffffffffu, ls1, 1);
        ls1 += __shfl_xor_sync(0xffffffffu, ls1, 2);
        l0 = l0*al0 + ls0; l1 = l1*al1 + ls1;
        if (t == 0){ sAl[mrow] = al0; sAl[mrow+8] = al1; }
        __syncthreads();

        float alo[4], ahi[4];
        #pragma unroll
        for (int mi=0;mi<4;mi++){ alo[mi]=sAl[mi*16+g]; ahi[mi]=sAl[mi*16+8+g]; }
        #pragma unroll
        for (int mi=0;mi<4;mi++)
            #pragma unroll
            for (int j=0;j<4;j++){
                o[mi][j][0]*=alo[mi]; o[mi][j][1]*=alo[mi];
                o[mi][j][2]*=ahi[mi]; o[mi][j][3]*=ahi[mi];
            }
        #pragma unroll
        for (int kb = 0; kb < 64; kb += 8) {
            uint32_t pf[4][4];
            #pragma unroll
            for (int mi=0;mi<4;mi++)
                ldsm4(pf[mi][0],pf[mi][1],pf[mi][2],pf[mi][3],
                      pu + poff0 + (uint32_t)(mi*16*68*4 + kb*4));
            #pragma unroll
            for (int j=0;j<4;j++){
                uint32_t b0 = ldb(&cKV[(kb+t  )*132 + wn + j*8 + g]);
                uint32_t b1 = ldb(&cKV[(kb+t+4)*132 + wn + j*8 + g]);
                #pragma unroll
                for (int mi=0;mi<4;mi++)
                    mma8(o[mi][j][0],o[mi][j][1],o[mi][j][2],o[mi][j][3],
                         pf[mi][0],pf[mi][1],pf[mi][2],pf[mi][3], b0,b1);
            }
        }
    }

    // ---------- fused value projection: v = O_norm @ W^T ----------
    if (t == 0){ sL[mrow] = l0; sL[mrow+8] = l1; }
    __syncthreads();                        // PV reads done, sL visible
    cp_wait<0>();                           // W resident in buffer (1-stO)
    const int stO = qt & 1;
    float* sO = sKV + stO*64*132;
    const uint32_t oB = kvu + (uint32_t)(stO*64*132*4);
    const uint32_t wB = kvu + (uint32_t)((1-stO)*64*132*4);

    #pragma unroll
    for (int mi=0;mi<4;mi++){
        int lr0 = mi*16 + g, lr1 = lr0 + 8;
        float inv0 = 1.f/sL[lr0], inv1 = 1.f/sL[lr1];
        #pragma unroll
        for (int j=0;j<4;j++){
            int col = wn + j*8 + 2*t;
            *(float2*)&sO[lr0*132 + col] = make_float2(rnd(o[mi][j][0]*inv0), rnd(o[mi][j][1]*inv0));
            *(float2*)&sO[lr1*132 + col] = make_float2(rnd(o[mi][j][2]*inv1), rnd(o[mi][j][3]*inv1));
        }
    }
    __syncthreads();

    {
        const int rw = w*16;
        const uint32_t aoffO = (uint32_t)(((rw + matr*8 + r8)*132 + matc*4)*4);
        float vo[8][4];
        #pragma unroll
        for (int j=0;j<8;j++){ vo[j][0]=0.f; vo[j][1]=0.f; vo[j][2]=0.f; vo[j][3]=0.f; }
        #pragma unroll
        for (int kk=0; kk<16; kk++){
            uint32_t a0,a1,a2,a3;
            ldsm4(a0,a1,a2,a3, oB + aoffO + (uint32_t)(kk*8*4));
            uint32_t wf[8][2];
            #pragma unroll
            for (int p=0;p<4;p++){
                uint32_t r0,r1,r2,r3;
                ldsm4(r0,r1,r2,r3, wB + koff0 + (uint32_t)(p*16*132*4 + kk*8*4));
                wf[2*p][0]=r0; wf[2*p][1]=r1; wf[2*p+1][0]=r2; wf[2*p+1][1]=r3;
            }
            #pragma unroll
            for (int j=0;j<8;j++)
                mma8(vo[j][0],vo[j][1],vo[j][2],vo[j][3], a0,a1,a2,a3, wf[j][0],wf[j][1]);
        }
        int grow = q0 + rw + g;
        #pragma unroll
        for (int j=0;j<8;j++){
            int col = h*NDV + j*8 + 2*t;
            size_t base0 = (size_t)(b*SQ + grow    )*(NH*NDV) + col;
            size_t base1 = (size_t)(b*SQ + grow + 8)*(NH*NDV) + col;
            *(float2*)&vout[base0] = make_float2(rnd(vo[j][0]), rnd(vo[j][1]));
            *(float2*)&vout[base1] = make_float2(rnd(vo[j][2]), rnd(vo[j][3]));
        }
    }
}

// ---------- launch ----------
extern "C" void kernel_launch(void* const* d_in, const int* in_sizes, int n_in,
                              void* d_out, int out_size)
{
    const float* h_ptr     = (const float*)d_in[0];
    const float* wq_a_w    = (const float*)d_in[2];
    const float* wq_a_b    = (const float*)d_in[3];
    const float* q_norm_w  = (const float*)d_in[4];
    const float* wq_b_w    = (const float*)d_in[5];
    const float* wq_b_b    = (const float*)d_in[6];
    const float* wkv_a_w   = (const float*)d_in[7];
    const float* wkv_a_b   = (const float*)d_in[8];
    const float* kv_norm_w = (const float*)d_in[9];
    const float* wkv_b_w   = (const float*)d_in[10];
    const float* wo_w      = (const float*)d_in[11];
    const float* wo_b      = (const float*)d_in[12];
    float* out = (float*)d_out;

    float *projcat, *qlat, *kvn, *qkv, *vv, *wc, *biasc, *worn, *wkvbv, *wcat, *bcat;
    cudaGetSymbolAddress((void**)&projcat, g_projcat);
    cudaGetSymbolAddress((void**)&qlat,  g_qlat);
    cudaGetSymbolAddress((void**)&kvn,   g_kvn);
    cudaGetSymbolAddress((void**)&qkv,   g_qkv);
    cudaGetSymbolAddress((void**)&vv,    g_v);
    cudaGetSymbolAddress((void**)&wc,    g_wc);
    cudaGetSymbolAddress((void**)&biasc, g_biasc);
    cudaGetSymbolAddress((void**)&worn,  g_worn);
    cudaGetSymbolAddress((void**)&wkvbv, g_wkvbv);
    cudaGetSymbolAddress((void**)&wcat,  g_wcat);
    cudaGetSymbolAddress((void**)&bcat,  g_bcat);

    const int gsm128 = 3*(128+128)*36*4;                   // 110592
    const int asm_   = (2*64*132 + 64*68 + 128)*4;         // 85504
    cudaFuncSetAttribute((tgemm3<128,true,true,false>),  cudaFuncAttributeMaxDynamicSharedMemorySize, gsm128);
    cudaFuncSetAttribute((tgemm3<128,false,true,false>), cudaFuncAttributeMaxDynamicSharedMemorySize, gsm128);
    cudaFuncSetAttribute((tgemm3<128,false,true,true>),  cudaFuncAttributeMaxDynamicSharedMemorySize, gsm128);
    cudaFuncSetAttribute(attn_tc, cudaFuncAttributeMaxDynamicSharedMemorySize, asm_);

    prep_weights<<<1536, 256>>>(wo_w, wkv_b_w, wq_a_w, wq_a_b, wkv_a_w, wkv_a_b,
                                worn, wkvbv, wcat, bcat);
    prep_wc_kernel<<<NH*DLKV, DLQ>>>(wq_b_w, wq_b_b, wkv_b_w, wc, biasc);

    // merged latent projections: [8192,1024] x [384,1024]^T (A = raw h, cvt in fragments)
    tgemm3<128,false,true,true><<<dim3(3, NTOK/128, 1), 256, gsm128>>>(
        h_ptr, DIM, 0, wcat, DIM, 0, bcat, projcat, 384, 0, DIM);
    rms2_kernel<<<NTOK, 128>>>(projcat, q_norm_w, kv_norm_w, qlat, kvn);

    // absorbed q -> latent-kv: [8192,256] x [2048,256]^T (rounded for attention)
    tgemm3<128,true,true,false><<<dim3(16, NTOK/128, 1), 256, gsm128>>>(
        qlat, DLQ, 0, wc, DLQ, 0, biasc, qkv, NH*DLKV, 0, DLQ);

    // attention + fused per-head value projection
    attn_tc<<<dim3(SQ/64, NH, BB), 128, asm_>>>(qkv, kvn, wkvbv, vv);

    // out = v @ wo_w^T + wo_b: [8192,1024] x [1024,1024]^T
    tgemm3<128,false,true,false><<<dim3(8, NTOK/128, 1), 256, gsm128>>>(
        vv, NH*NDV, 0, worn, NH*NDV, 0, wo_b, out, DIM, 0, NH*NDV);
}

// round 14
// speedup vs baseline: 1.1682x; 1.0157x over previous
#include <cuda_runtime.h>
#include <cstdint>

#define SQ   2048
#define BB   4
#define DIM  1024
#define NH   16
#define NDQK 20
#define NDV  64
#define DLQ  256
#define DLKV 128
#define NTOK (BB*SQ)

__device__ float g_projcat[(size_t)NTOK*384];
__device__ float g_qlat[NTOK*DLQ];
__device__ float g_kvn [NTOK*DLKV];
__device__ float g_qkv [(size_t)NTOK*NH*DLKV];
__device__ float g_v   [(size_t)NTOK*NH*NDV];
__device__ float g_wc  [NH*DLKV*DLQ];
__device__ float g_biasc[NH*DLKV];
__device__ float g_worn[DIM*NH*NDV];
__device__ float g_wkvbv[NH*NDV*DLKV];
__device__ float g_wcat[384*DIM];
__device__ float g_bcat[384];

// ======================= helpers =======================
__device__ __forceinline__ uint32_t f2tf(float f){
    uint32_t u; asm("cvt.rna.tf32.f32 %0, %1;" : "=r"(u) : "f"(f)); return u;
}
__device__ __forceinline__ float rnd(float f){ return __uint_as_float(f2tf(f)); }
__device__ __forceinline__ void mma8(float&c0,float&c1,float&c2,float&c3,
    uint32_t a0,uint32_t a1,uint32_t a2,uint32_t a3,uint32_t b0,uint32_t b1){
    asm volatile("mma.sync.aligned.m16n8k8.row.col.f32.tf32.tf32.f32 "
        "{%0,%1,%2,%3}, {%4,%5,%6,%7}, {%8,%9}, {%0,%1,%2,%3};"
        : "+f"(c0),"+f"(c1),"+f"(c2),"+f"(c3)
        : "r"(a0),"r"(a1),"r"(a2),"r"(a3),"r"(b0),"r"(b1));
}
__device__ __forceinline__ void ldsm4(uint32_t&r0,uint32_t&r1,uint32_t&r2,uint32_t&r3,uint32_t a){
    asm volatile("ldmatrix.sync.aligned.m8n8.x4.shared.b16 {%0,%1,%2,%3}, [%4];"
        : "=r"(r0),"=r"(r1),"=r"(r2),"=r"(r3) : "r"(a));
}
__device__ __forceinline__ uint32_t smem_u32(const void* p){
    uint32_t a;
    asm("{ .reg .u64 t; cvta.to.shared.u64 t, %1; cvt.u32.u64 %0, t; }" : "=r"(a) : "l"(p));
    return a;
}
__device__ __forceinline__ void cp16(uint32_t dst, const void* src){
    asm volatile("cp.async.cg.shared.global [%0], [%1], 16;" :: "r"(dst), "l"(src));
}
__device__ __forceinline__ void cp_commit(){ asm volatile("cp.async.commit_group;" ::: "memory"); }
template<int NW> __device__ __forceinline__ void cp_wait(){
    asm volatile("cp.async.wait_group %0;" :: "n"(NW) : "memory");
}
__device__ __forceinline__ uint32_t ldb(const float* p){ return __float_as_uint(*p); }

// ---------- merged weight prep ----------
// grid 1536: [0,1024) worn (float4), [1024,1152) wkvbv (float4), [1152,1536) wcat
__global__ void prep_weights(const float* __restrict__ wo_w, const float* __restrict__ wkv_b_w,
                             const float* __restrict__ wq_a_w, const float* __restrict__ wq_a_b,
                             const float* __restrict__ wkv_a_w, const float* __restrict__ wkv_a_b,
                             float* __restrict__ worn, float* __restrict__ wkvbv,
                             float* __restrict__ wcat, float* __restrict__ bcat){
    int bx = blockIdx.x;
    if (bx < 1024){
        size_t i = ((size_t)bx*256 + threadIdx.x)*4;
        float4 v = *(const float4*)&wo_w[i];
        v.x=rnd(v.x); v.y=rnd(v.y); v.z=rnd(v.z); v.w=rnd(v.w);
        *(float4*)&worn[i] = v;
    } else if (bx < 1152){
        int i = (bx-1024)*1024 + threadIdx.x*4;
        int h = i >> 13, rem = i & 8191;
        float4 v = *(const float4*)&wkv_b_w[(size_t)(h*(NDQK+NDV) + NDQK)*DLKV + rem];
        v.x=rnd(v.x); v.y=rnd(v.y); v.z=rnd(v.z); v.w=rnd(v.w);
        *(float4*)&wkvbv[i] = v;
    } else {
        int n = bx - 1152;
        const float* src = (n < 256) ? (wq_a_w + (size_t)n*DIM) : (wkv_a_w + (size_t)(n-256)*DIM);
        for (int k = threadIdx.x; k < DIM; k += 256) wcat[(size_t)n*DIM + k] = rnd(src[k]);
        if (threadIdx.x == 0) bcat[n] = (n < 256) ? wq_a_b[n] : wkv_a_b[n-256];
    }
}
__global__ void prep_wc_kernel(const float* __restrict__ wq_b_w,
                               const float* __restrict__ wq_b_b,
                               const float* __restrict__ wkv_b_w,
                               float* __restrict__ wc, float* __restrict__ biasc) {
    int hc = blockIdx.x, h = hc >> 7, c = hc & 127, l = threadIdx.x;
    float acc = 0.f, accb = 0.f;
    #pragma unroll
    for (int q = 0; q < NDQK; q++) {
        float kb = wkv_b_w[(size_t)(h*(NDQK+NDV) + q)*DLKV + c];
        acc  = fmaf(kb, wq_b_w[(size_t)(h*NDQK + q)*DLQ + l], acc);
        accb = fmaf(kb, wq_b_b[h*NDQK + q], accb);
    }
    wc[(size_t)hc*DLQ + l] = rnd(acc);
    if (l == 0) biasc[hc] = accb;
}

// ---------- merged RMSNorm, 2 rows per block (bit-identical per-row math) ----------
__global__ void rms2_kernel(const float* __restrict__ in,
                            const float* __restrict__ wq, const float* __restrict__ wkv,
                            float* __restrict__ outq, float* __restrict__ outkv) {
    int grp = threadIdx.x >> 7;              // 0 or 1
    int tid = threadIdx.x & 127;
    int row = blockIdx.x*2 + grp;
    const float* x = in + (size_t)row*384;
    float ssq = 0.f;
    for (int i = tid; i < 256; i += 128) { float v = x[i]; ssq = fmaf(v, v, ssq); }
    float xk = x[256 + tid];
    float ssk = xk*xk;
    #pragma unroll
    for (int d = 16; d; d >>= 1){
        ssq += __shfl_xor_sync(0xffffffffu, ssq, d);
        ssk += __shfl_xor_sync(0xffffffffu, ssk, d);
    }
    __shared__ float redq[8], redk[8];
    int wid = threadIdx.x >> 5;              // 0..7
    if ((tid & 31) == 0){ redq[wid] = ssq; redk[wid] = ssk; }
    __syncthreads();
    int rb = grp*4;
    float rq = rsqrtf((redq[rb]+redq[rb+1]+redq[rb+2]+redq[rb+3]) / 256.f + 1e-6f);
    float rk = rsqrtf((redk[rb]+redk[rb+1]+redk[rb+2]+redk[rb+3]) / 128.f + 1e-6f);
    for (int i = tid; i < 256; i += 128)
        outq[(size_t)row*256 + i] = rnd(x[i] * rq * wq[i]);
    outkv[(size_t)row*128 + tid] = rnd(xk * rk * wkv[tid]);
}

// ---------- tf32 mma GEMM, cp.async 3-stage, ldmatrix, z-batched ----------
template<int BN, bool ROUND, bool BIAS, bool CVTA>
__global__ __launch_bounds__(256, 2) void tgemm3(
    const float* __restrict__ A, int lda, size_t sAz,
    const float* __restrict__ Bm, int ldb, size_t sBz,
    const float* __restrict__ bias, float* __restrict__ C, int ldc, size_t sCz,
    int K)
{
    extern __shared__ float smem[];
    const int SSZ = (128+BN)*36;
    constexpr int NJ = BN/16;
    constexpr int NP = BN/32;

    const int mt = blockIdx.y*128, nt = blockIdx.x*BN;
    A  += (size_t)blockIdx.z*sAz;
    Bm += (size_t)blockIdx.z*sBz;
    C  += (size_t)blockIdx.z*sCz;

    const int tid = threadIdx.x, w = tid>>5, lane = tid&31;
    const int g = lane>>2, t = lane&3;
    const int wm = (w&3)*32, wn = (w>>2)*(BN/2);
    const int mat = lane>>3, r8 = lane&7;
    const int matr = mat&1, matc = mat>>1;

    const uint32_t smu = smem_u32(smem);
    const uint32_t aoff0 = (uint32_t)(((wm + matr*8 + r8)*36 + matc*4)*4);
    const uint32_t boff0 = (uint32_t)((128*36 + (wn + matc*8 + r8)*36 + matr*4)*4);

    float acc[2][NJ][4];
    #pragma unroll
    for (int i=0;i<2;i++)
        #pragma unroll
        for (int j=0;j<NJ;j++){ acc[i][j][0]=0.f; acc[i][j][1]=0.f; acc[i][j][2]=0.f; acc[i][j][3]=0.f; }

    const int NC = K >> 5;
    auto fetch = [&](int i, int slot){
        const int k0 = i << 5;
        float* dA = smem + slot*SSZ;
        float* dB = dA + 128*36;
        #pragma unroll
        for (int s2=0;s2<4;s2++){
            int v = tid + s2*256, r = v>>3, c4 = (v&7)<<2;
            cp16(smem_u32(&dA[r*36 + c4]), &A[(size_t)(mt+r)*lda + k0 + c4]);
        }
        #pragma unroll
        for (int s2=0;s2<BN/32;s2++){
            int v = tid + s2*256, r = v>>3, c4 = (v&7)<<2;
            cp16(smem_u32(&dB[r*36 + c4]), &Bm[(size_t)(nt+r)*ldb + k0 + c4]);
        }
        cp_commit();
    };
    fetch(0, 0);
    if (NC > 1) fetch(1, 1);

    for (int i=0;i<NC;i++){
        if (i == NC-1) cp_wait<0>(); else cp_wait<1>();
        __syncthreads();
        if (i+2 < NC) fetch(i+2, (i+2)%3);
        const uint32_t sb = smu + (uint32_t)((i%3)*SSZ*4);
        #pragma unroll
        for (int kk=0; kk<32; kk+=8){
            uint32_t af[2][4], bf[NJ][2];
            #pragma unroll
            for (int ii=0;ii<2;ii++){
                ldsm4(af[ii][0],af[ii][1],af[ii][2],af[ii][3],
                      sb + aoff0 + (uint32_t)(ii*16*36*4 + kk*4));
                if (CVTA){
                    af[ii][0]=f2tf(__uint_as_float(af[ii][0]));
                    af[ii][1]=f2tf(__uint_as_float(af[ii][1]));
                    af[ii][2]=f2tf(__uint_as_float(af[ii][2]));
                    af[ii][3]=f2tf(__uint_as_float(af[ii][3]));
                }
            }
            #pragma unroll
            for (int p=0;p<NP;p++){
                uint32_t r0,r1,r2,r3;
                ldsm4(r0,r1,r2,r3, sb + boff0 + (uint32_t)(p*16*36*4 + kk*4));
                bf[2*p][0]=r0; bf[2*p][1]=r1; bf[2*p+1][0]=r2; bf[2*p+1][1]=r3;
            }
            #pragma unroll
            for (int ii=0;ii<2;ii++)
                #pragma unroll
                for (int j=0;j<NJ;j++)
                    mma8(acc[ii][j][0],acc[ii][j][1],acc[ii][j][2],acc[ii][j][3],
                         af[ii][0],af[ii][1],af[ii][2],af[ii][3],bf[j][0],bf[j][1]);
        }
    }
    #pragma unroll
    for (int ii=0;ii<2;ii++){
        int row0 = mt + wm + ii*16 + g, row1 = row0 + 8;
        #pragma unroll
        for (int j=0;j<NJ;j++){
            int col = nt + wn + j*8 + 2*t;
            float b0v = BIAS ? bias[col] : 0.f, b1v = BIAS ? bias[col+1] : 0.f;
            float o00 = acc[ii][j][0]+b0v, o01 = acc[ii][j][1]+b1v;
            float o10 = acc[ii][j][2]+b0v, o11 = acc[ii][j][3]+b1v;
            if (ROUND){ o00=rnd(o00); o01=rnd(o01); o10=rnd(o10); o11=rnd(o11); }
            *(float2*)&C[(size_t)row0*ldc + col] = make_float2(o00, o01);
            *(float2*)&C[(size_t)row1*ldc + col] = make_float2(o10, o11);
        }
    }
}

// ---------- flash attention (64-row tiles, 2 CTA/SM) + fused value projection ----------
__global__ __launch_bounds__(128, 2) void attn_tc(
    const float* __restrict__ qkv, const float* __restrict__ kvn,
    const float* __restrict__ wkvbv, float* __restrict__ vout)
{
    extern __shared__ float smf[];
    float*    sKV = smf;                          // [2][64][132]
    uint32_t* sP  = (uint32_t*)(smf + 2*64*132);  // [64][68] tf32 bits
    float*    sAl = smf + 2*64*132 + 64*68;       // [64] alpha
    float*    sL  = sAl + 64;                     // [64] sum

    const int qt = (int)gridDim.x - 1 - (int)blockIdx.x;
    const int h = blockIdx.y, b = blockIdx.z;
    const int tid = threadIdx.x, w = tid>>5, lane = tid & 31;
    const int g = lane >> 2, t = lane & 3;
    const int mat = lane>>3, r8 = lane&7;
    const int matr = mat&1, matc = mat>>1;
    const int q0 = qt*64;
    const int mrow = w*16 + g;
    const int wn = w*32;
    const float scale = 0.22360679774997896f;

    const uint32_t kvu = smem_u32(sKV);
    const uint32_t pu  = smem_u32(sP);
    const uint32_t koff0 = (uint32_t)(((matc*8 + r8)*132 + matr*4)*4);
    const uint32_t poff0 = (uint32_t)(((matr*8 + r8)*68 + matc*4)*4);

    // prefetch KV tile 0 -> buffer 0
    {
        #pragma unroll
        for (int s2=0;s2<16;s2++){
            int v = tid + s2*128, r = v>>5, c4 = (v&31)<<2;
            cp16(smem_u32(&sKV[r*132 + c4]), &kvn[((size_t)(b*SQ + r))*128 + c4]);
        }
        cp_commit();
    }
    // stage Q tile (coalesced) -> buffer 1, lift fragments via ldsm
    {
        float* dstQ = sKV + 64*132;
        const float* qb = &qkv[((size_t)((b*SQ + q0)*NH + h))*128];
        #pragma unroll
        for (int s2=0;s2<16;s2++){
            int v = tid + s2*128, r = v>>5, c4 = (v&31)<<2;
            cp16(smem_u32(&dstQ[r*132 + c4]), qb + (size_t)r*(NH*128) + c4);
        }
        cp_commit();
    }
    cp_wait<0>();
    __syncthreads();
    uint32_t qf[16][4];
    {
        const uint32_t qB = kvu + (uint32_t)(64*132*4);
        const uint32_t qoff = (uint32_t)(((w*16 + matr*8 + r8)*132 + matc*4)*4);
        #pragma unroll
        for (int kk=0; kk<16; kk++)
            ldsm4(qf[kk][0],qf[kk][1],qf[kk][2],qf[kk][3], qB + qoff + (uint32_t)(kk*8*4));
    }

    float o[4][4][4];
    #pragma unroll
    for (int mi=0;mi<4;mi++)
        #pragma unroll
        for (int j=0;j<4;j++){ o[mi][j][0]=0.f; o[mi][j][1]=0.f; o[mi][j][2]=0.f; o[mi][j][3]=0.f; }
    float m0=-1e30f, m1=-1e30f, l0=0.f, l1=0.f;

    for (int kt = 0; kt <= qt; kt++) {
        const int st = kt & 1;
        __syncthreads();
        {
            float* dst = sKV + (1-st)*64*132;
            const float* src = (kt < qt)
                ? &kvn[((size_t)(b*SQ + (kt+1)*64))*128]
                : &wkvbv[(size_t)h*NDV*DLKV];
            #pragma unroll
            for (int s2=0;s2<16;s2++){
                int v = tid + s2*128, r = v>>5, c4 = (v&31)<<2;
                cp16(smem_u32(&dst[r*132 + c4]), src + (size_t)r*128 + c4);
            }
            cp_commit();
            cp_wait<1>();
        }
        __syncthreads();
        const float* cKV = sKV + st*64*132;
        const uint32_t kB = kvu + (uint32_t)(st*64*132*4);
        const int k0 = kt*64;

        float s[8][4];
        #pragma unroll
        for (int j = 0; j < 8; j++) { s[j][0]=0.f; s[j][1]=0.f; s[j][2]=0.f; s[j][3]=0.f; }
        #pragma unroll
        for (int kk = 0; kk < 16; kk++) {
            uint32_t bf[8][2];
            #pragma unroll
            for (int p=0;p<4;p++){
                uint32_t r0,r1,r2,r3;
                ldsm4(r0,r1,r2,r3, kB + koff0 + (uint32_t)(p*16*132*4 + kk*8*4));
                bf[2*p][0]=r0; bf[2*p][1]=r1; bf[2*p+1][0]=r2; bf[2*p+1][1]=r3;
            }
            #pragma unroll
            for (int j = 0; j < 8; j++)
                mma8(s[j][0],s[j][1],s[j][2],s[j][3], qf[kk][0],qf[kk][1],qf[kk][2],qf[kk][3],
                     bf[j][0],bf[j][1]);
        }

        const bool diag = (kt == qt);
        const int grow0 = q0 + mrow, grow1 = grow0 + 8;
        float mx0=-1e30f, mx1=-1e30f;
        #pragma unroll
        for (int j = 0; j < 8; j++) {
            int c = k0 + j*8 + 2*t;
            #pragma unroll
            for (int e = 0; e < 2; e++) {
                float v0 = s[j][e]*scale, v1 = s[j][2+e]*scale;
                if (diag && (c+e) > grow0) v0 = -1e30f;
                if (diag && (c+e) > grow1) v1 = -1e30f;
                s[j][e] = v0; s[j][2+e] = v1;
                mx0 = fmaxf(mx0, v0); mx1 = fmaxf(mx1, v1);
            }
        }
        mx0 = fmaxf(mx0, __shfl_xor_sync(0xffffffffu, mx0, 1));
        mx0 = fmaxf(mx0, __shfl_xor_sync(0xffffffffu, mx0, 2));
        mx1 = fmaxf(mx1, __shfl_xor_sync(0xffffffffu, mx1, 1));
        mx1 = fmaxf(mx1, __shfl_xor_sync(0xffffffffu, mx1, 2));
        float nm0 = fmaxf(m0, mx0), nm1 = fmaxf(m1, mx1);
        float al0 = __expf(m0 - nm0), al1 = __expf(m1 - nm1);
        m0 = nm0; m1 = nm1;
        float ls0 = 0.f, ls1 = 0.f;
        #pragma unroll
        for (int j = 0; j < 8; j++) {
            float p00 = __expf(s[j][0]-nm0), p01 = __expf(s[j][1]-nm0);
            float p10 = __expf(s[j][2]-nm1), p11 = __expf(s[j][3]-nm1);
            ls0 += p00 + p01; ls1 += p10 + p11;
            int c = j*8 + 2*t;
            sP[(mrow  )*68 + c] = f2tf(p00); sP[(mrow  )*68 + c+1] = f2tf(p01);
            sP[(mrow+8)*68 + c] = f2tf(p10); sP[(mrow+8)*68 + c+1] = f2tf(p11);
        }
        ls0 += __shfl_xor_sync(0xffffffffu, ls0, 1);
        ls0 += __shfl_xor_sync(0xffffffffu, ls0, 2);
        ls1 += __shfl_xor_sync(0xffffffffu, ls1, 1);
        ls1 += __shfl_xor_sync(0xffffffffu, ls1, 2);
        l0 = l0*al0 + ls0; l1 = l1*al1 + ls1;
        if (t == 0){ sAl[mrow] = al0; sAl[mrow+8] = al1; }
        __syncthreads();

        float alo[4], ahi[4];
        #pragma unroll
        for (int mi=0;mi<4;mi++){ alo[mi]=sAl[mi*16+g]; ahi[mi]=sAl[mi*16+8+g]; }
        #pragma unroll
        for (int mi=0;mi<4;mi++)
            #pragma unroll
            for (int j=0;j<4;j++){
                o[mi][j][0]*=alo[mi]; o[mi][j][1]*=alo[mi];
                o[mi][j][2]*=ahi[mi]; o[mi][j][3]*=ahi[mi];
            }
        #pragma unroll
        for (int kb = 0; kb < 64; kb += 8) {
            uint32_t pf[4][4];
            #pragma unroll
            for (int mi=0;mi<4;mi++)
                ldsm4(pf[mi][0],pf[mi][1],pf[mi][2],pf[mi][3],
                      pu + poff0 + (uint32_t)(mi*16*68*4 + kb*4));
            #pragma unroll
            for (int j=0;j<4;j++){
                uint32_t b0 = ldb(&cKV[(kb+t  )*132 + wn + j*8 + g]);
                uint32_t b1 = ldb(&cKV[(kb+t+4)*132 + wn + j*8 + g]);
                #pragma unroll
                for (int mi=0;mi<4;mi++)
                    mma8(o[mi][j][0],o[mi][j][1],o[mi][j][2],o[mi][j][3],
                         pf[mi][0],pf[mi][1],pf[mi][2],pf[mi][3], b0,b1);
            }
        }
    }

    // ---------- fused value projection: v = O_norm @ W^T ----------
    if (t == 0){ sL[mrow] = l0; sL[mrow+8] = l1; }
    __syncthreads();
    cp_wait<0>();
    const int stO = qt & 1;
    float* sO = sKV + stO*64*132;
    const uint32_t oB = kvu + (uint32_t)(stO*64*132*4);
    const uint32_t wB = kvu + (uint32_t)((1-stO)*64*132*4);

    #pragma unroll
    for (int mi=0;mi<4;mi++){
        int lr0 = mi*16 + g, lr1 = lr0 + 8;
        float inv0 = 1.f/sL[lr0], inv1 = 1.f/sL[lr1];
        #pragma unroll
        for (int j=0;j<4;j++){
            int col = wn + j*8 + 2*t;
            *(float2*)&sO[lr0*132 + col] = make_float2(rnd(o[mi][j][0]*inv0), rnd(o[mi][j][1]*inv0));
            *(float2*)&sO[lr1*132 + col] = make_float2(rnd(o[mi][j][2]*inv1), rnd(o[mi][j][3]*inv1));
        }
    }
    __syncthreads();

    {
        const int rw = w*16;
        const uint32_t aoffO = (uint32_t)(((rw + matr*8 + r8)*132 + matc*4)*4);
        float vo[8][4];
        #pragma unroll
        for (int j=0;j<8;j++){ vo[j][0]=0.f; vo[j][1]=0.f; vo[j][2]=0.f; vo[j][3]=0.f; }
        #pragma unroll
        for (int kk=0; kk<16; kk++){
            uint32_t a0,a1,a2,a3;
            ldsm4(a0,a1,a2,a3, oB + aoffO + (uint32_t)(kk*8*4));
            uint32_t wf[8][2];
            #pragma unroll
            for (int p=0;p<4;p++){
                uint32_t r0,r1,r2,r3;
                ldsm4(r0,r1,r2,r3, wB + koff0 + (uint32_t)(p*16*132*4 + kk*8*4));
                wf[2*p][0]=r0; wf[2*p][1]=r1; wf[2*p+1][0]=r2; wf[2*p+1][1]=r3;
            }
            #pragma unroll
            for (int j=0;j<8;j++)
                mma8(vo[j][0],vo[j][1],vo[j][2],vo[j][3], a0,a1,a2,a3, wf[j][0],wf[j][1]);
        }
        int grow = q0 + rw + g;
        #pragma unroll
        for (int j=0;j<8;j++){
            int col = h*NDV + j*8 + 2*t;
            size_t base0 = (size_t)(b*SQ + grow    )*(NH*NDV) + col;
            size_t base1 = (size_t)(b*SQ + grow + 8)*(NH*NDV) + col;
            *(float2*)&vout[base0] = make_float2(rnd(vo[j][0]), rnd(vo[j][1]));
            *(float2*)&vout[base1] = make_float2(rnd(vo[j][2]), rnd(vo[j][3]));
        }
    }
}

// ---------- launch ----------
extern "C" void kernel_launch(void* const* d_in, const int* in_sizes, int n_in,
                              void* d_out, int out_size)
{
    const float* h_ptr     = (const float*)d_in[0];
    const float* wq_a_w    = (const float*)d_in[2];
    const float* wq_a_b    = (const float*)d_in[3];
    const float* q_norm_w  = (const float*)d_in[4];
    const float* wq_b_w    = (const float*)d_in[5];
    const float* wq_b_b    = (const float*)d_in[6];
    const float* wkv_a_w   = (const float*)d_in[7];
    const float* wkv_a_b   = (const float*)d_in[8];
    const float* kv_norm_w = (const float*)d_in[9];
    const float* wkv_b_w   = (const float*)d_in[10];
    const float* wo_w      = (const float*)d_in[11];
    const float* wo_b      = (const float*)d_in[12];
    float* out = (float*)d_out;

    float *projcat, *qlat, *kvn, *qkv, *vv, *wc, *biasc, *worn, *wkvbv, *wcat, *bcat;
    cudaGetSymbolAddress((void**)&projcat, g_projcat);
    cudaGetSymbolAddress((void**)&qlat,  g_qlat);
    cudaGetSymbolAddress((void**)&kvn,   g_kvn);
    cudaGetSymbolAddress((void**)&qkv,   g_qkv);
    cudaGetSymbolAddress((void**)&vv,    g_v);
    cudaGetSymbolAddress((void**)&wc,    g_wc);
    cudaGetSymbolAddress((void**)&biasc, g_biasc);
    cudaGetSymbolAddress((void**)&worn,  g_worn);
    cudaGetSymbolAddress((void**)&wkvbv, g_wkvbv);
    cudaGetSymbolAddress((void**)&wcat,  g_wcat);
    cudaGetSymbolAddress((void**)&bcat,  g_bcat);

    const int gsm128 = 3*(128+128)*36*4;                   // 110592
    const int gsm96  = 3*(128+96)*36*4;                    // 96768
    const int asm_   = (2*64*132 + 64*68 + 128)*4;         // 85504
    cudaFuncSetAttribute((tgemm3<128,true,true,false>),  cudaFuncAttributeMaxDynamicSharedMemorySize, gsm128);
    cudaFuncSetAttribute((tgemm3<128,false,true,false>), cudaFuncAttributeMaxDynamicSharedMemorySize, gsm128);
    cudaFuncSetAttribute((tgemm3<96,false,true,true>),   cudaFuncAttributeMaxDynamicSharedMemorySize, gsm96);
    cudaFuncSetAttribute(attn_tc, cudaFuncAttributeMaxDynamicSharedMemorySize, asm_);

    prep_weights<<<1536, 256>>>(wo_w, wkv_b_w, wq_a_w, wq_a_b, wkv_a_w, wkv_a_b,
                                worn, wkvbv, wcat, bcat);
    prep_wc_kernel<<<NH*DLKV, DLQ>>>(wq_b_w, wq_b_b, wkv_b_w, wc, biasc);

    // merged latent projections: [8192,1024] x [384,1024]^T  (BN=96: one full wave)
    tgemm3<96,false,true,true><<<dim3(4, NTOK/128, 1), 256, gsm96>>>(
        h_ptr, DIM, 0, wcat, DIM, 0, bcat, projcat, 384, 0, DIM);
    rms2_kernel<<<NTOK/2, 256>>>(projcat, q_norm_w, kv_norm_w, qlat, kvn);

    // absorbed q -> latent-kv: [8192,256] x [2048,256]^T (rounded for attention)
    tgemm3<128,true,true,false><<<dim3(16, NTOK/128, 1), 256, gsm128>>>(
        qlat, DLQ, 0, wc, DLQ, 0, biasc, qkv, NH*DLKV, 0, DLQ);

    // attention + fused per-head value projection
    attn_tc<<<dim3(SQ/64, NH, BB), 128, asm_>>>(qkv, kvn, wkvbv, vv);

    // out = v @ wo_w^T + wo_b: [8192,1024] x [1024,1024]^T
    tgemm3<128,false,true,false><<<dim3(8, NTOK/128, 1), 256, gsm128>>>(
        vv, NH*NDV, 0, worn, NH*NDV, 0, wo_b, out, DIM, 0, NH*NDV);
}

// round 16
// speedup vs baseline: 1.3877x; 1.1880x over previous
#include <cuda_runtime.h>
#include <cstdint>

#define SQ   2048
#define BB   4
#define DIM  1024
#define NH   16
#define NDQK 20
#define NDV  64
#define DLQ  256
#define DLKV 128
#define NTOK (BB*SQ)
#define QH32 32
#define KHS  36
#define VS   132
#define BUF  (64*KHS + 64*VS)

__device__ float g_projcat[(size_t)NTOK*384];
__device__ float g_qlat[NTOK*DLQ];
__device__ float g_kvn [NTOK*DLKV];
__device__ float g_qh  [(size_t)NTOK*NH*QH32];
__device__ float g_kh  [(size_t)NTOK*NH*QH32];
__device__ float g_v   [(size_t)NTOK*NH*NDV];
__device__ float g_worn[DIM*NH*NDV];
__device__ float g_wkvbv[NH*NDV*DLKV];
__device__ float g_wcat[384*DIM];
__device__ float g_bcat[384];
__device__ float g_wqbp[NH*QH32*DLQ];
__device__ float g_bqp [NH*QH32];
__device__ float g_wkp [NH*QH32*DLKV];

// ======================= helpers =======================
__device__ __forceinline__ uint32_t f2tf(float f){
    uint32_t u; asm("cvt.rna.tf32.f32 %0, %1;" : "=r"(u) : "f"(f)); return u;
}
__device__ __forceinline__ float rnd(float f){ return __uint_as_float(f2tf(f)); }
__device__ __forceinline__ void mma8(float&c0,float&c1,float&c2,float&c3,
    uint32_t a0,uint32_t a1,uint32_t a2,uint32_t a3,uint32_t b0,uint32_t b1){
    asm volatile("mma.sync.aligned.m16n8k8.row.col.f32.tf32.tf32.f32 "
        "{%0,%1,%2,%3}, {%4,%5,%6,%7}, {%8,%9}, {%0,%1,%2,%3};"
        : "+f"(c0),"+f"(c1),"+f"(c2),"+f"(c3)
        : "r"(a0),"r"(a1),"r"(a2),"r"(a3),"r"(b0),"r"(b1));
}
__device__ __forceinline__ void ldsm4(uint32_t&r0,uint32_t&r1,uint32_t&r2,uint32_t&r3,uint32_t a){
    asm volatile("ldmatrix.sync.aligned.m8n8.x4.shared.b16 {%0,%1,%2,%3}, [%4];"
        : "=r"(r0),"=r"(r1),"=r"(r2),"=r"(r3) : "r"(a));
}
__device__ __forceinline__ uint32_t smem_u32(const void* p){
    uint32_t a;
    asm("{ .reg .u64 t; cvta.to.shared.u64 t, %1; cvt.u32.u64 %0, t; }" : "=r"(a) : "l"(p));
    return a;
}
__device__ __forceinline__ void cp16(uint32_t dst, const void* src){
    asm volatile("cp.async.cg.shared.global [%0], [%1], 16;" :: "r"(dst), "l"(src));
}
__device__ __forceinline__ void cp_commit(){ asm volatile("cp.async.commit_group;" ::: "memory"); }
template<int NW> __device__ __forceinline__ void cp_wait(){
    asm volatile("cp.async.wait_group %0;" :: "n"(NW) : "memory");
}
__device__ __forceinline__ uint32_t ldb(const float* p){ return __float_as_uint(*p); }

// ---------- merged weight prep ----------
__global__ void prep_weights(const float* __restrict__ wo_w, const float* __restrict__ wkv_b_w,
                             const float* __restrict__ wq_a_w, const float* __restrict__ wq_a_b,
                             const float* __restrict__ wkv_a_w, const float* __restrict__ wkv_a_b,
                             float* __restrict__ worn, float* __restrict__ wkvbv,
                             float* __restrict__ wcat, float* __restrict__ bcat){
    int bx = blockIdx.x;
    if (bx < 1024){
        size_t i = ((size_t)bx*256 + threadIdx.x)*4;
        float4 v = *(const float4*)&wo_w[i];
        v.x=rnd(v.x); v.y=rnd(v.y); v.z=rnd(v.z); v.w=rnd(v.w);
        *(float4*)&worn[i] = v;
    } else if (bx < 1152){
        int i = (bx-1024)*1024 + threadIdx.x*4;
        int h = i >> 13, rem = i & 8191;
        float4 v = *(const float4*)&wkv_b_w[(size_t)(h*(NDQK+NDV) + NDQK)*DLKV + rem];
        v.x=rnd(v.x); v.y=rnd(v.y); v.z=rnd(v.z); v.w=rnd(v.w);
        *(float4*)&wkvbv[i] = v;
    } else {
        int n = bx - 1152;
        const float* src = (n < 256) ? (wq_a_w + (size_t)n*DIM) : (wkv_a_w + (size_t)(n-256)*DIM);
        for (int k = threadIdx.x; k < DIM; k += 256) wcat[(size_t)n*DIM + k] = rnd(src[k]);
        if (threadIdx.x == 0) bcat[n] = (n < 256) ? wq_a_b[n] : wkv_a_b[n-256];
    }
}
__global__ void prep_qk(const float* __restrict__ wq_b_w, const float* __restrict__ wq_b_b,
                        const float* __restrict__ wkv_b_w,
                        float* __restrict__ wqbp, float* __restrict__ bqp,
                        float* __restrict__ wkp){
    int n = blockIdx.x;
    if (n < NH*QH32){
        int h = n >> 5, qq = n & 31;
        if (qq < NDQK){
            for (int k = threadIdx.x; k < DLQ; k += 256)
                wqbp[(size_t)n*DLQ + k] = rnd(wq_b_w[(size_t)(h*NDQK + qq)*DLQ + k]);
            if (threadIdx.x == 0) bqp[n] = wq_b_b[h*NDQK + qq];
        } else {
            for (int k = threadIdx.x; k < DLQ; k += 256) wqbp[(size_t)n*DLQ + k] = 0.f;
            if (threadIdx.x == 0) bqp[n] = 0.f;
        }
    } else {
        int m = n - NH*QH32;
        int h = m >> 5, qq = m & 31;
        if (threadIdx.x < DLKV)
            wkp[(size_t)m*DLKV + threadIdx.x] = (qq < NDQK)
                ? rnd(wkv_b_w[(size_t)(h*(NDQK+NDV) + qq)*DLKV + threadIdx.x]) : 0.f;
    }
}

// ---------- merged RMSNorm, 2 rows per block ----------
__global__ void rms2_kernel(const float* __restrict__ in,
                            const float* __restrict__ wq, const float* __restrict__ wkv,
                            float* __restrict__ outq, float* __restrict__ outkv) {
    int grp = threadIdx.x >> 7;
    int tid = threadIdx.x & 127;
    int row = blockIdx.x*2 + grp;
    const float* x = in + (size_t)row*384;
    float ssq = 0.f;
    for (int i = tid; i < 256; i += 128) { float v = x[i]; ssq = fmaf(v, v, ssq); }
    float xk = x[256 + tid];
    float ssk = xk*xk;
    #pragma unroll
    for (int d = 16; d; d >>= 1){
        ssq += __shfl_xor_sync(0xffffffffu, ssq, d);
        ssk += __shfl_xor_sync(0xffffffffu, ssk, d);
    }
    __shared__ float redq[8], redk[8];
    int wid = threadIdx.x >> 5;
    if ((tid & 31) == 0){ redq[wid] = ssq; redk[wid] = ssk; }
    __syncthreads();
    int rb = grp*4;
    float rq = rsqrtf((redq[rb]+redq[rb+1]+redq[rb+2]+redq[rb+3]) / 256.f + 1e-6f);
    float rk = rsqrtf((redk[rb]+redk[rb+1]+redk[rb+2]+redk[rb+3]) / 128.f + 1e-6f);
    for (int i = tid; i < 256; i += 128)
        outq[(size_t)row*256 + i] = rnd(x[i] * rq * wq[i]);
    outkv[(size_t)row*128 + tid] = rnd(xk * rk * wkv[tid]);
}

// ---------- tf32 mma GEMM, cp.async 3-stage, ldmatrix ----------
template<int BN, bool ROUND, bool BIAS, bool CVTA>
__global__ __launch_bounds__(256, 2) void tgemm3(
    const float* __restrict__ A, int lda, size_t sAz,
    const float* __restrict__ Bm, int ldb, size_t sBz,
    const float* __restrict__ bias, float* __restrict__ C, int ldc, size_t sCz,
    int K)
{
    extern __shared__ float smem[];
    const int SSZ = (128+BN)*36;
    constexpr int NJ = BN/16;
    constexpr int NP = BN/32;

    const int mt = blockIdx.y*128, nt = blockIdx.x*BN;
    A  += (size_t)blockIdx.z*sAz;
    Bm += (size_t)blockIdx.z*sBz;
    C  += (size_t)blockIdx.z*sCz;

    const int tid = threadIdx.x, w = tid>>5, lane = tid&31;
    const int g = lane>>2, t = lane&3;
    const int wm = (w&3)*32, wn = (w>>2)*(BN/2);
    const int mat = lane>>3, r8 = lane&7;
    const int matr = mat&1, matc = mat>>1;

    const uint32_t smu = smem_u32(smem);
    const uint32_t aoff0 = (uint32_t)(((wm + matr*8 + r8)*36 + matc*4)*4);
    const uint32_t boff0 = (uint32_t)((128*36 + (wn + matc*8 + r8)*36 + matr*4)*4);

    float acc[2][NJ][4];
    #pragma unroll
    for (int i=0;i<2;i++)
        #pragma unroll
        for (int j=0;j<NJ;j++){ acc[i][j][0]=0.f; acc[i][j][1]=0.f; acc[i][j][2]=0.f; acc[i][j][3]=0.f; }

    const int NC = K >> 5;
    auto fetch = [&](int i, int slot){
        const int k0 = i << 5;
        float* dA = smem + slot*SSZ;
        float* dB = dA + 128*36;
        #pragma unroll
        for (int s2=0;s2<4;s2++){
            int v = tid + s2*256, r = v>>3, c4 = (v&7)<<2;
            cp16(smem_u32(&dA[r*36 + c4]), &A[(size_t)(mt+r)*lda + k0 + c4]);
        }
        #pragma unroll
        for (int s2=0;s2<BN/32;s2++){
            int v = tid + s2*256, r = v>>3, c4 = (v&7)<<2;
            cp16(smem_u32(&dB[r*36 + c4]), &Bm[(size_t)(nt+r)*ldb + k0 + c4]);
        }
        cp_commit();
    };
    fetch(0, 0);
    if (NC > 1) fetch(1, 1);

    for (int i=0;i<NC;i++){
        if (i == NC-1) cp_wait<0>(); else cp_wait<1>();
        __syncthreads();
        if (i+2 < NC) fetch(i+2, (i+2)%3);
        const uint32_t sb = smu + (uint32_t)((i%3)*SSZ*4);
        #pragma unroll
        for (int kk=0; kk<32; kk+=8){
            uint32_t af[2][4], bf[NJ][2];
            #pragma unroll
            for (int ii=0;ii<2;ii++){
                ldsm4(af[ii][0],af[ii][1],af[ii][2],af[ii][3],
                      sb + aoff0 + (uint32_t)(ii*16*36*4 + kk*4));
                if (CVTA){
                    af[ii][0]=f2tf(__uint_as_float(af[ii][0]));
                    af[ii][1]=f2tf(__uint_as_float(af[ii][1]));
                    af[ii][2]=f2tf(__uint_as_float(af[ii][2]));
                    af[ii][3]=f2tf(__uint_as_float(af[ii][3]));
                }
            }
            #pragma unroll
            for (int p=0;p<NP;p++){
                uint32_t r0,r1,r2,r3;
                ldsm4(r0,r1,r2,r3, sb + boff0 + (uint32_t)(p*16*36*4 + kk*4));
                bf[2*p][0]=r0; bf[2*p][1]=r1; bf[2*p+1][0]=r2; bf[2*p+1][1]=r3;
            }
            #pragma unroll
            for (int ii=0;ii<2;ii++)
                #pragma unroll
                for (int j=0;j<NJ;j++)
                    mma8(acc[ii][j][0],acc[ii][j][1],acc[ii][j][2],acc[ii][j][3],
                         af[ii][0],af[ii][1],af[ii][2],af[ii][3],bf[j][0],bf[j][1]);
        }
    }
    #pragma unroll
    for (int ii=0;ii<2;ii++){
        int row0 = mt + wm + ii*16 + g, row1 = row0 + 8;
        #pragma unroll
        for (int j=0;j<NJ;j++){
            int col = nt + wn + j*8 + 2*t;
            float b0v = BIAS ? bias[col] : 0.f, b1v = BIAS ? bias[col+1] : 0.f;
            float o00 = acc[ii][j][0]+b0v, o01 = acc[ii][j][1]+b1v;
            float o10 = acc[ii][j][2]+b0v, o11 = acc[ii][j][3]+b1v;
            if (ROUND){ o00=rnd(o00); o01=rnd(o01); o10=rnd(o10); o11=rnd(o11); }
            *(float2*)&C[(size_t)row0*ldc + col] = make_float2(o00, o01);
            *(float2*)&C[(size_t)row1*ldc + col] = make_float2(o10, o11);
        }
    }
}

// ---------- flash attention: rank-20 score path, fused value projection ----------
__global__ __launch_bounds__(128, 2) void attn_tc(
    const float* __restrict__ qh, const float* __restrict__ kh,
    const float* __restrict__ kvn, const float* __restrict__ wkvbv,
    float* __restrict__ vout)
{
    extern __shared__ float smf[];
    float*    sKV = smf;                          // 2 x BUF
    uint32_t* sP  = (uint32_t*)(smf + 2*BUF);     // [64][68]
    float*    sAl = smf + 2*BUF + 64*68;
    float*    sL  = sAl + 64;

    const int qt = (int)gridDim.x - 1 - (int)blockIdx.x;
    const int h = blockIdx.y, b = blockIdx.z;
    const int tid = threadIdx.x, w = tid>>5, lane = tid & 31;
    const int g = lane >> 2, t = lane & 3;
    const int mat = lane>>3, r8 = lane&7;
    const int matr = mat&1, matc = mat>>1;
    const int q0 = qt*64;
    const int mrow = w*16 + g;
    const int wn = w*32;
    const float scale = 0.22360679774997896f;

    const uint32_t kvu = smem_u32(sKV);
    const uint32_t pu  = smem_u32(sP);
    const uint32_t koffK = (uint32_t)(((matc*8 + r8)*KHS + matr*4)*4);
    const uint32_t koffV = (uint32_t)(((matc*8 + r8)*VS  + matr*4)*4);
    const uint32_t poff0 = (uint32_t)(((matr*8 + r8)*68 + matc*4)*4);

    // prefetch tile 0 -> buffer 0 (kh: 64x32, kvn: 64x128)
    {
        const float* ks = &kh [((size_t)(b*SQ))*(NH*QH32) + h*QH32];
        #pragma unroll
        for (int s2=0;s2<4;s2++){
            int v = tid + s2*128, r = v>>3, c4 = (v&7)<<2;
            cp16(smem_u32(&sKV[r*KHS + c4]), ks + (size_t)r*(NH*QH32) + c4);
        }
        const float* vs = &kvn[((size_t)(b*SQ))*128];
        float* dv = sKV + 64*KHS;
        #pragma unroll
        for (int s2=0;s2<16;s2++){
            int v = tid + s2*128, r = v>>5, c4 = (v&31)<<2;
            cp16(smem_u32(&dv[r*VS + c4]), vs + (size_t)r*128 + c4);
        }
        cp_commit();
    }
    // stage Q tile (64 x 32) -> buffer 1 kh region
    {
        float* dstQ = sKV + BUF;
        const float* qb = &qh[((size_t)(b*SQ + q0))*(NH*QH32) + h*QH32];
        #pragma unroll
        for (int s2=0;s2<4;s2++){
            int v = tid + s2*128, r = v>>3, c4 = (v&7)<<2;
            cp16(smem_u32(&dstQ[r*KHS + c4]), qb + (size_t)r*(NH*QH32) + c4);
        }
        cp_commit();
    }
    cp_wait<0>();
    __syncthreads();
    uint32_t qf[3][4];
    {
        const uint32_t qB = kvu + (uint32_t)(BUF*4);
        const uint32_t qoff = (uint32_t)(((w*16 + matr*8 + r8)*KHS + matc*4)*4);
        #pragma unroll
        for (int kk=0; kk<3; kk++)
            ldsm4(qf[kk][0],qf[kk][1],qf[kk][2],qf[kk][3], qB + qoff + (uint32_t)(kk*32));
    }

    float o[4][4][4];
    #pragma unroll
    for (int mi=0;mi<4;mi++)
        #pragma unroll
        for (int j=0;j<4;j++){ o[mi][j][0]=0.f; o[mi][j][1]=0.f; o[mi][j][2]=0.f; o[mi][j][3]=0.f; }
    float m0=-1e30f, m1=-1e30f, l0=0.f, l1=0.f;

    for (int kt = 0; kt <= qt; kt++) {
        const int st = kt & 1;
        __syncthreads();
        {   // prefetch next tile (kh 64x32 + kvn 64x128), or W (64x128) on last tile
            float* dst = sKV + (1-st)*BUF;
            if (kt < qt){
                const int k0n = (kt+1)*64;
                const float* ks = &kh [((size_t)(b*SQ + k0n))*(NH*QH32) + h*QH32];
                #pragma unroll
                for (int s2=0;s2<4;s2++){
                    int v = tid + s2*128, r = v>>3, c4 = (v&7)<<2;
                    cp16(smem_u32(&dst[r*KHS + c4]), ks + (size_t)r*(NH*QH32) + c4);
                }
                const float* vs = &kvn[((size_t)(b*SQ + k0n))*128];
                float* dv = dst + 64*KHS;
                #pragma unroll
                for (int s2=0;s2<16;s2++){
                    int v = tid + s2*128, r = v>>5, c4 = (v&31)<<2;
                    cp16(smem_u32(&dv[r*VS + c4]), vs + (size_t)r*128 + c4);
                }
            } else {
                float* dv = dst + 64*KHS;
                const float* ws = &wkvbv[(size_t)h*NDV*DLKV];
                #pragma unroll
                for (int s2=0;s2<16;s2++){
                    int v = tid + s2*128, r = v>>5, c4 = (v&31)<<2;
                    cp16(smem_u32(&dv[r*VS + c4]), ws + (size_t)r*128 + c4);
                }
            }
            cp_commit();
            cp_wait<1>();
        }
        __syncthreads();
        const float* cV = sKV + st*BUF + 64*KHS;
        const uint32_t kBk = kvu + (uint32_t)(st*BUF*4);
        const int k0 = kt*64;

        // S = q @ k^T : 3 k-chunks (24 effective)
        float s[8][4];
        #pragma unroll
        for (int j = 0; j < 8; j++) { s[j][0]=0.f; s[j][1]=0.f; s[j][2]=0.f; s[j][3]=0.f; }
        #pragma unroll
        for (int kk = 0; kk < 3; kk++) {
            uint32_t bf[8][2];
            #pragma unroll
            for (int p=0;p<4;p++){
                uint32_t r0,r1,r2,r3;
                ldsm4(r0,r1,r2,r3, kBk + koffK + (uint32_t)(p*16*KHS*4 + kk*32));
                bf[2*p][0]=r0; bf[2*p][1]=r1; bf[2*p+1][0]=r2; bf[2*p+1][1]=r3;
            }
            #pragma unroll
            for (int j = 0; j < 8; j++)
                mma8(s[j][0],s[j][1],s[j][2],s[j][3], qf[kk][0],qf[kk][1],qf[kk][2],qf[kk][3],
                     bf[j][0],bf[j][1]);
        }

        const bool diag = (kt == qt);
        const int grow0 = q0 + mrow, grow1 = grow0 + 8;
        float mx0=-1e30f, mx1=-1e30f;
        #pragma unroll
        for (int j = 0; j < 8; j++) {
            int c = k0 + j*8 + 2*t;
            #pragma unroll
            for (int e = 0; e < 2; e++) {
                float v0 = s[j][e]*scale, v1 = s[j][2+e]*scale;
                if (diag && (c+e) > grow0) v0 = -1e30f;
                if (diag && (c+e) > grow1) v1 = -1e30f;
                s[j][e] = v0; s[j][2+e] = v1;
                mx0 = fmaxf(mx0, v0); mx1 = fmaxf(mx1, v1);
            }
        }
        mx0 = fmaxf(mx0, __shfl_xor_sync(0xffffffffu, mx0, 1));
        mx0 = fmaxf(mx0, __shfl_xor_sync(0xffffffffu, mx0, 2));
        mx1 = fmaxf(mx1, __shfl_xor_sync(0xffffffffu, mx1, 1));
        mx1 = fmaxf(mx1, __shfl_xor_sync(0xffffffffu, mx1, 2));
        float nm0 = fmaxf(m0, mx0), nm1 = fmaxf(m1, mx1);
        float al0 = __expf(m0 - nm0), al1 = __expf(m1 - nm1);
        m0 = nm0; m1 = nm1;
        float ls0 = 0.f, ls1 = 0.f;
        #pragma unroll
        for (int j = 0; j < 8; j++) {
            float p00 = __expf(s[j][0]-nm0), p01 = __expf(s[j][1]-nm0);
            float p10 = __expf(s[j][2]-nm1), p11 = __expf(s[j][3]-nm1);
            ls0 += p00 + p01; ls1 += p10 + p11;
            int c = j*8 + 2*t;
            sP[(mrow  )*68 + c] = f2tf(p00); sP[(mrow  )*68 + c+1] = f2tf(p01);
            sP[(mrow+8)*68 + c] = f2tf(p10); sP[(mrow+8)*68 + c+1] = f2tf(p11);
        }
        ls0 += __shfl_xor_sync(0xffffffffu, ls0, 1);
        ls0 += __shfl_xor_sync(0xffffffffu, ls0, 2);
        ls1 += __shfl_xor_sync(0xffffffffu, ls1, 1);
        ls1 += __shfl_xor_sync(0xffffffffu, ls1, 2);
        l0 = l0*al0 + ls0; l1 = l1*al1 + ls1;
        if (t == 0){ sAl[mrow] = al0; sAl[mrow+8] = al1; }
        __syncthreads();

        float alo[4], ahi[4];
        #pragma unroll
        for (int mi=0;mi<4;mi++){ alo[mi]=sAl[mi*16+g]; ahi[mi]=sAl[mi*16+8+g]; }
        #pragma unroll
        for (int mi=0;mi<4;mi++)
            #pragma unroll
            for (int j=0;j<4;j++){
                o[mi][j][0]*=alo[mi]; o[mi][j][1]*=alo[mi];
                o[mi][j][2]*=ahi[mi]; o[mi][j][3]*=ahi[mi];
            }
        #pragma unroll
        for (int kb = 0; kb < 64; kb += 8) {
            uint32_t pf[4][4];
            #pragma unroll
            for (int mi=0;mi<4;mi++)
                ldsm4(pf[mi][0],pf[mi][1],pf[mi][2],pf[mi][3],
                      pu + poff0 + (uint32_t)(mi*16*68*4 + kb*4));
            #pragma unroll
            for (int j=0;j<4;j++){
                uint32_t b0 = ldb(&cV[(kb+t  )*VS + wn + j*8 + g]);
                uint32_t b1 = ldb(&cV[(kb+t+4)*VS + wn + j*8 + g]);
                #pragma unroll
                for (int mi=0;mi<4;mi++)
                    mma8(o[mi][j][0],o[mi][j][1],o[mi][j][2],o[mi][j][3],
                         pf[mi][0],pf[mi][1],pf[mi][2],pf[mi][3], b0,b1);
            }
        }
    }

    // ---------- fused value projection ----------
    if (t == 0){ sL[mrow] = l0; sL[mrow+8] = l1; }
    __syncthreads();
    cp_wait<0>();
    const int stO = qt & 1;
    float* sO = sKV + stO*BUF + 64*KHS;
    const uint32_t oB = kvu + (uint32_t)((stO*BUF + 64*KHS)*4);
    const uint32_t wB = kvu + (uint32_t)(((1-stO)*BUF + 64*KHS)*4);

    #pragma unroll
    for (int mi=0;mi<4;mi++){
        int lr0 = mi*16 + g, lr1 = lr0 + 8;
        float inv0 = 1.f/sL[lr0], inv1 = 1.f/sL[lr1];
        #pragma unroll
        for (int j=0;j<4;j++){
            int col = wn + j*8 + 2*t;
            *(float2*)&sO[lr0*VS + col] = make_float2(rnd(o[mi][j][0]*inv0), rnd(o[mi][j][1]*inv0));
            *(float2*)&sO[lr1*VS + col] = make_float2(rnd(o[mi][j][2]*inv1), rnd(o[mi][j][3]*inv1));
        }
    }
    __syncthreads();

    {
        const int rw = w*16;
        const uint32_t aoffO = (uint32_t)(((rw + matr*8 + r8)*VS + matc*4)*4);
        float vo[8][4];
        #pragma unroll
        for (int j=0;j<8;j++){ vo[j][0]=0.f; vo[j][1]=0.f; vo[j][2]=0.f; vo[j][3]=0.f; }
        #pragma unroll
        for (int kk=0; kk<16; kk++){
            uint32_t a0,a1,a2,a3;
            ldsm4(a0,a1,a2,a3, oB + aoffO + (uint32_t)(kk*8*4));
            uint32_t wf[8][2];
            #pragma unroll
            for (int p=0;p<4;p++){
                uint32_t r0,r1,r2,r3;
                ldsm4(r0,r1,r2,r3, wB + koffV + (uint32_t)(p*16*VS*4 + kk*8*4));
                wf[2*p][0]=r0; wf[2*p][1]=r1; wf[2*p+1][0]=r2; wf[2*p+1][1]=r3;
            }
            #pragma unroll
            for (int j=0;j<8;j++)
                mma8(vo[j][0],vo[j][1],vo[j][2],vo[j][3], a0,a1,a2,a3, wf[j][0],wf[j][1]);
        }
        int grow = q0 + rw + g;
        #pragma unroll
        for (int j=0;j<8;j++){
            int col = h*NDV + j*8 + 2*t;
            size_t base0 = (size_t)(b*SQ + grow    )*(NH*NDV) + col;
            size_t base1 = (size_t)(b*SQ + grow + 8)*(NH*NDV) + col;
            *(float2*)&vout[base0] = make_float2(rnd(vo[j][0]), rnd(vo[j][1]));
            *(float2*)&vout[base1] = make_float2(rnd(vo[j][2]), rnd(vo[j][3]));
        }
    }
}

// ---------- launch ----------
extern "C" void kernel_launch(void* const* d_in, const int* in_sizes, int n_in,
                              void* d_out, int out_size)
{
    const float* h_ptr     = (const float*)d_in[0];
    const float* wq_a_w    = (const float*)d_in[2];
    const float* wq_a_b    = (const float*)d_in[3];
    const float* q_norm_w  = (const float*)d_in[4];
    const float* wq_b_w    = (const float*)d_in[5];
    const float* wq_b_b    = (const float*)d_in[6];
    const float* wkv_a_w   = (const float*)d_in[7];
    const float* wkv_a_b   = (const float*)d_in[8];
    const float* kv_norm_w = (const float*)d_in[9];
    const float* wkv_b_w   = (const float*)d_in[10];
    const float* wo_w      = (const float*)d_in[11];
    const float* wo_b      = (const float*)d_in[12];
    float* out = (float*)d_out;

    float *projcat, *qlat, *kvn, *qhp, *khp, *vv, *worn, *wkvbv, *wcat, *bcat, *wqbp, *bqp, *wkp;
    cudaGetSymbolAddress((void**)&projcat, g_projcat);
    cudaGetSymbolAddress((void**)&qlat,  g_qlat);
    cudaGetSymbolAddress((void**)&kvn,   g_kvn);
    cudaGetSymbolAddress((void**)&qhp,   g_qh);
    cudaGetSymbolAddress((void**)&khp,   g_kh);
    cudaGetSymbolAddress((void**)&vv,    g_v);
    cudaGetSymbolAddress((void**)&worn,  g_worn);
    cudaGetSymbolAddress((void**)&wkvbv, g_wkvbv);
    cudaGetSymbolAddress((void**)&wcat,  g_wcat);
    cudaGetSymbolAddress((void**)&bcat,  g_bcat);
    cudaGetSymbolAddress((void**)&wqbp,  g_wqbp);
    cudaGetSymbolAddress((void**)&bqp,   g_bqp);
    cudaGetSymbolAddress((void**)&wkp,   g_wkp);

    const int gsm128 = 3*(128+128)*36*4;
    const int gsm96  = 3*(128+96)*36*4;
    const int asm_   = (2*BUF + 64*68 + 128)*4;             // 103936
    cudaFuncSetAttribute((tgemm3<128,false,true,false>), cudaFuncAttributeMaxDynamicSharedMemorySize, gsm128);
    cudaFuncSetAttribute((tgemm3<128,true,true,false>),  cudaFuncAttributeMaxDynamicSharedMemorySize, gsm128);
    cudaFuncSetAttribute((tgemm3<128,true,false,false>), cudaFuncAttributeMaxDynamicSharedMemorySize, gsm128);
    cudaFuncSetAttribute((tgemm3<96,false,true,true>),   cudaFuncAttributeMaxDynamicSharedMemorySize, gsm96);
    cudaFuncSetAttribute(attn_tc, cudaFuncAttributeMaxDynamicSharedMemorySize, asm_);

    prep_weights<<<1536, 256>>>(wo_w, wkv_b_w, wq_a_w, wq_a_b, wkv_a_w, wkv_a_b,
                                worn, wkvbv, wcat, bcat);
    prep_qk<<<2*NH*QH32, 256>>>(wq_b_w, wq_b_b, wkv_b_w, wqbp, bqp, wkp);

    tgemm3<96,false,true,true><<<dim3(4, NTOK/128, 1), 256, gsm96>>>(
        h_ptr, DIM, 0, wcat, DIM, 0, bcat, projcat, 384, 0, DIM);
    rms2_kernel<<<NTOK/2, 256>>>(projcat, q_norm_w, kv_norm_w, qlat, kvn);

    tgemm3<128,true,true,false><<<dim3(4, NTOK/128, 1), 256, gsm128>>>(
        qlat, DLQ, 0, wqbp, DLQ, 0, bqp, qhp, NH*QH32, 0, DLQ);
    tgemm3<128,true,false,false><<<dim3(4, NTOK/128, 1), 256, gsm128>>>(
        kvn, DLKV, 0, wkp, DLKV, 0, nullptr, khp, NH*QH32, 0, DLKV);

    attn_tc<<<dim3(SQ/64, NH, BB), 128, asm_>>>(qhp, khp, kvn, wkvbv, vv);

    tgemm3<128,false,true,false><<<dim3(8, NTOK/128, 1), 256, gsm128>>>(
        vv, NH*NDV, 0, worn, NH*NDV, 0, wo_b, out, DIM, 0, NH*NDV);
}

// round 17
// speedup vs baseline: 1.7141x; 1.2352x over previous
#include <cuda_runtime.h>
#include <cstdint>

#define SQ   2048
#define BB   4
#define DIM  1024
#define NH   16
#define NDQK 20
#define NDV  64
#define DLQ  256
#define DLKV 128
#define NTOK (BB*SQ)
#define QH32 32
#define KHS  36
#define VHS  68
#define BUF  (64*KHS + 64*VHS)   /* 6656 floats per stage */

__device__ float g_projcat[(size_t)NTOK*384];
__device__ float g_qlat[NTOK*DLQ];
__device__ float g_kvn [NTOK*DLKV];
__device__ float g_qh  [(size_t)NTOK*NH*QH32];
__device__ float g_kh  [(size_t)NTOK*NH*QH32];
__device__ float g_vh  [(size_t)NTOK*NH*NDV];
__device__ float g_v   [(size_t)NTOK*NH*NDV];
__device__ float g_worn[DIM*NH*NDV];
__device__ float g_wkvbv[NH*NDV*DLKV];
__device__ float g_wcat[384*DIM];
__device__ float g_bcat[384];
__device__ float g_wqbp[NH*QH32*DLQ];
__device__ float g_bqp [NH*QH32];
__device__ float g_wkp [NH*QH32*DLKV];

// ======================= helpers =======================
__device__ __forceinline__ uint32_t f2tf(float f){
    uint32_t u; asm("cvt.rna.tf32.f32 %0, %1;" : "=r"(u) : "f"(f)); return u;
}
__device__ __forceinline__ float rnd(float f){ return __uint_as_float(f2tf(f)); }
__device__ __forceinline__ void mma8(float&c0,float&c1,float&c2,float&c3,
    uint32_t a0,uint32_t a1,uint32_t a2,uint32_t a3,uint32_t b0,uint32_t b1){
    asm volatile("mma.sync.aligned.m16n8k8.row.col.f32.tf32.tf32.f32 "
        "{%0,%1,%2,%3}, {%4,%5,%6,%7}, {%8,%9}, {%0,%1,%2,%3};"
        : "+f"(c0),"+f"(c1),"+f"(c2),"+f"(c3)
        : "r"(a0),"r"(a1),"r"(a2),"r"(a3),"r"(b0),"r"(b1));
}
__device__ __forceinline__ void ldsm4(uint32_t&r0,uint32_t&r1,uint32_t&r2,uint32_t&r3,uint32_t a){
    asm volatile("ldmatrix.sync.aligned.m8n8.x4.shared.b16 {%0,%1,%2,%3}, [%4];"
        : "=r"(r0),"=r"(r1),"=r"(r2),"=r"(r3) : "r"(a));
}
__device__ __forceinline__ uint32_t smem_u32(const void* p){
    uint32_t a;
    asm("{ .reg .u64 t; cvta.to.shared.u64 t, %1; cvt.u32.u64 %0, t; }" : "=r"(a) : "l"(p));
    return a;
}
__device__ __forceinline__ void cp16(uint32_t dst, const void* src){
    asm volatile("cp.async.cg.shared.global [%0], [%1], 16;" :: "r"(dst), "l"(src));
}
__device__ __forceinline__ void cp_commit(){ asm volatile("cp.async.commit_group;" ::: "memory"); }
template<int NW> __device__ __forceinline__ void cp_wait(){
    asm volatile("cp.async.wait_group %0;" :: "n"(NW) : "memory");
}
__device__ __forceinline__ uint32_t ldb(const float* p){ return __float_as_uint(*p); }

// ---------- merged weight prep ----------
__global__ void prep_weights(const float* __restrict__ wo_w, const float* __restrict__ wkv_b_w,
                             const float* __restrict__ wq_a_w, const float* __restrict__ wq_a_b,
                             const float* __restrict__ wkv_a_w, const float* __restrict__ wkv_a_b,
                             float* __restrict__ worn, float* __restrict__ wkvbv,
                             float* __restrict__ wcat, float* __restrict__ bcat){
    int bx = blockIdx.x;
    if (bx < 1024){
        size_t i = ((size_t)bx*256 + threadIdx.x)*4;
        float4 v = *(const float4*)&wo_w[i];
        v.x=rnd(v.x); v.y=rnd(v.y); v.z=rnd(v.z); v.w=rnd(v.w);
        *(float4*)&worn[i] = v;
    } else if (bx < 1152){
        int i = (bx-1024)*1024 + threadIdx.x*4;
        int h = i >> 13, rem = i & 8191;
        float4 v = *(const float4*)&wkv_b_w[(size_t)(h*(NDQK+NDV) + NDQK)*DLKV + rem];
        v.x=rnd(v.x); v.y=rnd(v.y); v.z=rnd(v.z); v.w=rnd(v.w);
        *(float4*)&wkvbv[i] = v;
    } else {
        int n = bx - 1152;
        const float* src = (n < 256) ? (wq_a_w + (size_t)n*DIM) : (wkv_a_w + (size_t)(n-256)*DIM);
        for (int k = threadIdx.x; k < DIM; k += 256) wcat[(size_t)n*DIM + k] = rnd(src[k]);
        if (threadIdx.x == 0) bcat[n] = (n < 256) ? wq_a_b[n] : wkv_a_b[n-256];
    }
}
__global__ void prep_qk(const float* __restrict__ wq_b_w, const float* __restrict__ wq_b_b,
                        const float* __restrict__ wkv_b_w,
                        float* __restrict__ wqbp, float* __restrict__ bqp,
                        float* __restrict__ wkp){
    int n = blockIdx.x;
    if (n < NH*QH32){
        int h = n >> 5, qq = n & 31;
        if (qq < NDQK){
            for (int k = threadIdx.x; k < DLQ; k += 256)
                wqbp[(size_t)n*DLQ + k] = rnd(wq_b_w[(size_t)(h*NDQK + qq)*DLQ + k]);
            if (threadIdx.x == 0) bqp[n] = wq_b_b[h*NDQK + qq];
        } else {
            for (int k = threadIdx.x; k < DLQ; k += 256) wqbp[(size_t)n*DLQ + k] = 0.f;
            if (threadIdx.x == 0) bqp[n] = 0.f;
        }
    } else {
        int m = n - NH*QH32;
        int h = m >> 5, qq = m & 31;
        if (threadIdx.x < DLKV)
            wkp[(size_t)m*DLKV + threadIdx.x] = (qq < NDQK)
                ? rnd(wkv_b_w[(size_t)(h*(NDQK+NDV) + qq)*DLKV + threadIdx.x]) : 0.f;
    }
}

// ---------- merged RMSNorm, 2 rows per block ----------
__global__ void rms2_kernel(const float* __restrict__ in,
                            const float* __restrict__ wq, const float* __restrict__ wkv,
                            float* __restrict__ outq, float* __restrict__ outkv) {
    int grp = threadIdx.x >> 7;
    int tid = threadIdx.x & 127;
    int row = blockIdx.x*2 + grp;
    const float* x = in + (size_t)row*384;
    float ssq = 0.f;
    for (int i = tid; i < 256; i += 128) { float v = x[i]; ssq = fmaf(v, v, ssq); }
    float xk = x[256 + tid];
    float ssk = xk*xk;
    #pragma unroll
    for (int d = 16; d; d >>= 1){
        ssq += __shfl_xor_sync(0xffffffffu, ssq, d);
        ssk += __shfl_xor_sync(0xffffffffu, ssk, d);
    }
    __shared__ float redq[8], redk[8];
    int wid = threadIdx.x >> 5;
    if ((tid & 31) == 0){ redq[wid] = ssq; redk[wid] = ssk; }
    __syncthreads();
    int rb = grp*4;
    float rq = rsqrtf((redq[rb]+redq[rb+1]+redq[rb+2]+redq[rb+3]) / 256.f + 1e-6f);
    float rk = rsqrtf((redk[rb]+redk[rb+1]+redk[rb+2]+redk[rb+3]) / 128.f + 1e-6f);
    for (int i = tid; i < 256; i += 128)
        outq[(size_t)row*256 + i] = rnd(x[i] * rq * wq[i]);
    outkv[(size_t)row*128 + tid] = rnd(xk * rk * wkv[tid]);
}

// ---------- tf32 mma GEMM, cp.async 3-stage, ldmatrix ----------
template<int BN, bool ROUND, bool BIAS, bool CVTA>
__global__ __launch_bounds__(256, 2) void tgemm3(
    const float* __restrict__ A, int lda, size_t sAz,
    const float* __restrict__ Bm, int ldb, size_t sBz,
    const float* __restrict__ bias, float* __restrict__ C, int ldc, size_t sCz,
    int K)
{
    extern __shared__ float smem[];
    const int SSZ = (128+BN)*36;
    constexpr int NJ = BN/16;
    constexpr int NP = BN/32;

    const int mt = blockIdx.y*128, nt = blockIdx.x*BN;
    A  += (size_t)blockIdx.z*sAz;
    Bm += (size_t)blockIdx.z*sBz;
    C  += (size_t)blockIdx.z*sCz;

    const int tid = threadIdx.x, w = tid>>5, lane = tid&31;
    const int g = lane>>2, t = lane&3;
    const int wm = (w&3)*32, wn = (w>>2)*(BN/2);
    const int mat = lane>>3, r8 = lane&7;
    const int matr = mat&1, matc = mat>>1;

    const uint32_t smu = smem_u32(smem);
    const uint32_t aoff0 = (uint32_t)(((wm + matr*8 + r8)*36 + matc*4)*4);
    const uint32_t boff0 = (uint32_t)((128*36 + (wn + matc*8 + r8)*36 + matr*4)*4);

    float acc[2][NJ][4];
    #pragma unroll
    for (int i=0;i<2;i++)
        #pragma unroll
        for (int j=0;j<NJ;j++){ acc[i][j][0]=0.f; acc[i][j][1]=0.f; acc[i][j][2]=0.f; acc[i][j][3]=0.f; }

    const int NC = K >> 5;
    auto fetch = [&](int i, int slot){
        const int k0 = i << 5;
        float* dA = smem + slot*SSZ;
        float* dB = dA + 128*36;
        #pragma unroll
        for (int s2=0;s2<4;s2++){
            int v = tid + s2*256, r = v>>3, c4 = (v&7)<<2;
            cp16(smem_u32(&dA[r*36 + c4]), &A[(size_t)(mt+r)*lda + k0 + c4]);
        }
        #pragma unroll
        for (int s2=0;s2<BN/32;s2++){
            int v = tid + s2*256, r = v>>3, c4 = (v&7)<<2;
            cp16(smem_u32(&dB[r*36 + c4]), &Bm[(size_t)(nt+r)*ldb + k0 + c4]);
        }
        cp_commit();
    };
    fetch(0, 0);
    if (NC > 1) fetch(1, 1);

    for (int i=0;i<NC;i++){
        if (i == NC-1) cp_wait<0>(); else cp_wait<1>();
        __syncthreads();
        if (i+2 < NC) fetch(i+2, (i+2)%3);
        const uint32_t sb = smu + (uint32_t)((i%3)*SSZ*4);
        #pragma unroll
        for (int kk=0; kk<32; kk+=8){
            uint32_t af[2][4], bf[NJ][2];
            #pragma unroll
            for (int ii=0;ii<2;ii++){
                ldsm4(af[ii][0],af[ii][1],af[ii][2],af[ii][3],
                      sb + aoff0 + (uint32_t)(ii*16*36*4 + kk*4));
                if (CVTA){
                    af[ii][0]=f2tf(__uint_as_float(af[ii][0]));
                    af[ii][1]=f2tf(__uint_as_float(af[ii][1]));
                    af[ii][2]=f2tf(__uint_as_float(af[ii][2]));
                    af[ii][3]=f2tf(__uint_as_float(af[ii][3]));
                }
            }
            #pragma unroll
            for (int p=0;p<NP;p++){
                uint32_t r0,r1,r2,r3;
                ldsm4(r0,r1,r2,r3, sb + boff0 + (uint32_t)(p*16*36*4 + kk*4));
                bf[2*p][0]=r0; bf[2*p][1]=r1; bf[2*p+1][0]=r2; bf[2*p+1][1]=r3;
            }
            #pragma unroll
            for (int ii=0;ii<2;ii++)
                #pragma unroll
                for (int j=0;j<NJ;j++)
                    mma8(acc[ii][j][0],acc[ii][j][1],acc[ii][j][2],acc[ii][j][3],
                         af[ii][0],af[ii][1],af[ii][2],af[ii][3],bf[j][0],bf[j][1]);
        }
    }
    #pragma unroll
    for (int ii=0;ii<2;ii++){
        int row0 = mt + wm + ii*16 + g, row1 = row0 + 8;
        #pragma unroll
        for (int j=0;j<NJ;j++){
            int col = nt + wn + j*8 + 2*t;
            float b0v = BIAS ? bias[col] : 0.f, b1v = BIAS ? bias[col+1] : 0.f;
            float o00 = acc[ii][j][0]+b0v, o01 = acc[ii][j][1]+b1v;
            float o10 = acc[ii][j][2]+b0v, o11 = acc[ii][j][3]+b1v;
            if (ROUND){ o00=rnd(o00); o01=rnd(o01); o10=rnd(o10); o11=rnd(o11); }
            *(float2*)&C[(size_t)row0*ldc + col] = make_float2(o00, o01);
            *(float2*)&C[(size_t)row1*ldc + col] = make_float2(o10, o11);
        }
    }
}

// ---------- flash attention: rank-20 scores, 64-dim per-head values, 3 CTA/SM ----------
__global__ __launch_bounds__(128, 3) void attn_tc(
    const float* __restrict__ qh, const float* __restrict__ kh,
    const float* __restrict__ vh, float* __restrict__ vout)
{
    extern __shared__ float smf[];
    float*    sKV = smf;                          // 2 x BUF (kh 64x36 + vh 64x68)
    uint32_t* sP  = (uint32_t*)(smf + 2*BUF);     // [64][68]
    float*    sAl = smf + 2*BUF + 64*68;
    float*    sL  = sAl + 64;

    const int qt = (int)gridDim.x - 1 - (int)blockIdx.x;
    const int h = blockIdx.y, b = blockIdx.z;
    const int tid = threadIdx.x, w = tid>>5, lane = tid & 31;
    const int g = lane >> 2, t = lane & 3;
    const int mat = lane>>3, r8 = lane&7;
    const int matr = mat&1, matc = mat>>1;
    const int q0 = qt*64;
    const int mrow = w*16 + g;
    const int wn = w*16;                  // PV column ownership (16 of 64)
    const float scale = 0.22360679774997896f;

    const uint32_t kvu = smem_u32(sKV);
    const uint32_t pu  = smem_u32(sP);
    const uint32_t koffK = (uint32_t)(((matc*8 + r8)*KHS + matr*4)*4);
    const uint32_t poff0 = (uint32_t)(((matr*8 + r8)*68 + matc*4)*4);

    // prefetch tile 0 -> buffer 0 (kh 64x32, vh 64x64)
    {
        const float* ks = &kh[((size_t)(b*SQ))*(NH*QH32) + h*QH32];
        #pragma unroll
        for (int s2=0;s2<4;s2++){
            int v = tid + s2*128, r = v>>3, c4 = (v&7)<<2;
            cp16(smem_u32(&sKV[r*KHS + c4]), ks + (size_t)r*(NH*QH32) + c4);
        }
        const float* vs = &vh[((size_t)(b*SQ))*(NH*NDV) + h*NDV];
        float* dv = sKV + 64*KHS;
        #pragma unroll
        for (int s2=0;s2<8;s2++){
            int v = tid + s2*128, r = v>>4, c4 = (v&15)<<2;
            cp16(smem_u32(&dv[r*VHS + c4]), vs + (size_t)r*(NH*NDV) + c4);
        }
        cp_commit();
    }
    // stage Q tile (64 x 32) -> buffer 1 kh region
    {
        float* dstQ = sKV + BUF;
        const float* qb = &qh[((size_t)(b*SQ + q0))*(NH*QH32) + h*QH32];
        #pragma unroll
        for (int s2=0;s2<4;s2++){
            int v = tid + s2*128, r = v>>3, c4 = (v&7)<<2;
            cp16(smem_u32(&dstQ[r*KHS + c4]), qb + (size_t)r*(NH*QH32) + c4);
        }
        cp_commit();
    }
    cp_wait<0>();
    __syncthreads();
    uint32_t qf[3][4];
    {
        const uint32_t qB = kvu + (uint32_t)(BUF*4);
        const uint32_t qoff = (uint32_t)(((w*16 + matr*8 + r8)*KHS + matc*4)*4);
        #pragma unroll
        for (int kk=0; kk<3; kk++)
            ldsm4(qf[kk][0],qf[kk][1],qf[kk][2],qf[kk][3], qB + qoff + (uint32_t)(kk*32));
    }

    float o[4][2][4];
    #pragma unroll
    for (int mi=0;mi<4;mi++)
        #pragma unroll
        for (int j=0;j<2;j++){ o[mi][j][0]=0.f; o[mi][j][1]=0.f; o[mi][j][2]=0.f; o[mi][j][3]=0.f; }
    float m0=-1e30f, m1=-1e30f, l0=0.f, l1=0.f;

    for (int kt = 0; kt <= qt; kt++) {
        const int st = kt & 1;
        __syncthreads();
        if (kt < qt) {
            const int k0n = (kt+1)*64;
            float* dst = sKV + (1-st)*BUF;
            const float* ks = &kh[((size_t)(b*SQ + k0n))*(NH*QH32) + h*QH32];
            #pragma unroll
            for (int s2=0;s2<4;s2++){
                int v = tid + s2*128, r = v>>3, c4 = (v&7)<<2;
                cp16(smem_u32(&dst[r*KHS + c4]), ks + (size_t)r*(NH*QH32) + c4);
            }
            const float* vs = &vh[((size_t)(b*SQ + k0n))*(NH*NDV) + h*NDV];
            float* dv = dst + 64*KHS;
            #pragma unroll
            for (int s2=0;s2<8;s2++){
                int v = tid + s2*128, r = v>>4, c4 = (v&15)<<2;
                cp16(smem_u32(&dv[r*VHS + c4]), vs + (size_t)r*(NH*NDV) + c4);
            }
            cp_commit();
            cp_wait<1>();
        } else {
            cp_wait<0>();
        }
        __syncthreads();
        const float* cVh = sKV + st*BUF + 64*KHS;
        const uint32_t kBk = kvu + (uint32_t)(st*BUF*4);
        const int k0 = kt*64;

        // S = q @ k^T : 3 k-chunks
        float s[8][4];
        #pragma unroll
        for (int j = 0; j < 8; j++) { s[j][0]=0.f; s[j][1]=0.f; s[j][2]=0.f; s[j][3]=0.f; }
        #pragma unroll
        for (int kk = 0; kk < 3; kk++) {
            uint32_t bf[8][2];
            #pragma unroll
            for (int p=0;p<4;p++){
                uint32_t r0,r1,r2,r3;
                ldsm4(r0,r1,r2,r3, kBk + koffK + (uint32_t)(p*16*KHS*4 + kk*32));
                bf[2*p][0]=r0; bf[2*p][1]=r1; bf[2*p+1][0]=r2; bf[2*p+1][1]=r3;
            }
            #pragma unroll
            for (int j = 0; j < 8; j++)
                mma8(s[j][0],s[j][1],s[j][2],s[j][3], qf[kk][0],qf[kk][1],qf[kk][2],qf[kk][3],
                     bf[j][0],bf[j][1]);
        }

        const bool diag = (kt == qt);
        const int grow0 = q0 + mrow, grow1 = grow0 + 8;
        float mx0=-1e30f, mx1=-1e30f;
        #pragma unroll
        for (int j = 0; j < 8; j++) {
            int c = k0 + j*8 + 2*t;
            #pragma unroll
            for (int e = 0; e < 2; e++) {
                float v0 = s[j][e]*scale, v1 = s[j][2+e]*scale;
                if (diag && (c+e) > grow0) v0 = -1e30f;
                if (diag && (c+e) > grow1) v1 = -1e30f;
                s[j][e] = v0; s[j][2+e] = v1;
                mx0 = fmaxf(mx0, v0); mx1 = fmaxf(mx1, v1);
            }
        }
        mx0 = fmaxf(mx0, __shfl_xor_sync(0xffffffffu, mx0, 1));
        mx0 = fmaxf(mx0, __shfl_xor_sync(0xffffffffu, mx0, 2));
        mx1 = fmaxf(mx1, __shfl_xor_sync(0xffffffffu, mx1, 1));
        mx1 = fmaxf(mx1, __shfl_xor_sync(0xffffffffu, mx1, 2));
        float nm0 = fmaxf(m0, mx0), nm1 = fmaxf(m1, mx1);
        float al0 = __expf(m0 - nm0), al1 = __expf(m1 - nm1);
        m0 = nm0; m1 = nm1;
        float ls0 = 0.f, ls1 = 0.f;
        #pragma unroll
        for (int j = 0; j < 8; j++) {
            float p00 = __expf(s[j][0]-nm0), p01 = __expf(s[j][1]-nm0);
            float p10 = __expf(s[j][2]-nm1), p11 = __expf(s[j][3]-nm1);
            ls0 += p00 + p01; ls1 += p10 + p11;
            int c = j*8 + 2*t;
            sP[(mrow  )*68 + c] = f2tf(p00); sP[(mrow  )*68 + c+1] = f2tf(p01);
            sP[(mrow+8)*68 + c] = f2tf(p10); sP[(mrow+8)*68 + c+1] = f2tf(p11);
        }
        ls0 += __shfl_xor_sync(0xffffffffu, ls0, 1);
        ls0 += __shfl_xor_sync(0xffffffffu, ls0, 2);
        ls1 += __shfl_xor_sync(0xffffffffu, ls1, 1);
        ls1 += __shfl_xor_sync(0xffffffffu, ls1, 2);
        l0 = l0*al0 + ls0; l1 = l1*al1 + ls1;
        if (t == 0){ sAl[mrow] = al0; sAl[mrow+8] = al1; }
        __syncthreads();

        // PV column-partitioned: warp owns cols [wn, wn+16) of 64 for ALL rows
        #pragma unroll
        for (int mi=0;mi<4;mi++){
            float alo = sAl[mi*16+g], ahi = sAl[mi*16+8+g];
            #pragma unroll
            for (int j=0;j<2;j++){
                o[mi][j][0]*=alo; o[mi][j][1]*=alo;
                o[mi][j][2]*=ahi; o[mi][j][3]*=ahi;
            }
        }
        #pragma unroll
        for (int kb = 0; kb < 64; kb += 8) {
            uint32_t b0a = ldb(&cVh[(kb+t  )*VHS + wn + g]);
            uint32_t b1a = ldb(&cVh[(kb+t+4)*VHS + wn + g]);
            uint32_t b0b = ldb(&cVh[(kb+t  )*VHS + wn + 8 + g]);
            uint32_t b1b = ldb(&cVh[(kb+t+4)*VHS + wn + 8 + g]);
            #pragma unroll
            for (int mi=0;mi<4;mi++){
                uint32_t p0,p1,p2,p3;
                ldsm4(p0,p1,p2,p3, pu + poff0 + (uint32_t)(mi*16*68*4 + kb*4));
                mma8(o[mi][0][0],o[mi][0][1],o[mi][0][2],o[mi][0][3], p0,p1,p2,p3, b0a,b1a);
                mma8(o[mi][1][0],o[mi][1][1],o[mi][1][2],o[mi][1][3], p0,p1,p2,p3, b0b,b1b);
            }
        }
    }

    // ---------- normalize + write out directly (64-dim) ----------
    if (t == 0){ sL[mrow] = l0; sL[mrow+8] = l1; }
    __syncthreads();
    #pragma unroll
    for (int mi=0;mi<4;mi++){
        int lr0 = mi*16 + g, lr1 = lr0 + 8;
        float inv0 = 1.f/sL[lr0], inv1 = 1.f/sL[lr1];
        #pragma unroll
        for (int j=0;j<2;j++){
            int col = h*NDV + wn + j*8 + 2*t;
            size_t base0 = (size_t)(b*SQ + q0 + lr0)*(NH*NDV) + col;
            size_t base1 = (size_t)(b*SQ + q0 + lr1)*(NH*NDV) + col;
            *(float2*)&vout[base0] = make_float2(rnd(o[mi][j][0]*inv0), rnd(o[mi][j][1]*inv0));
            *(float2*)&vout[base1] = make_float2(rnd(o[mi][j][2]*inv1), rnd(o[mi][j][3]*inv1));
        }
    }
}

// ---------- launch ----------
extern "C" void kernel_launch(void* const* d_in, const int* in_sizes, int n_in,
                              void* d_out, int out_size)
{
    const float* h_ptr     = (const float*)d_in[0];
    const float* wq_a_w    = (const float*)d_in[2];
    const float* wq_a_b    = (const float*)d_in[3];
    const float* q_norm_w  = (const float*)d_in[4];
    const float* wq_b_w    = (const float*)d_in[5];
    const float* wq_b_b    = (const float*)d_in[6];
    const float* wkv_a_w   = (const float*)d_in[7];
    const float* wkv_a_b   = (const float*)d_in[8];
    const float* kv_norm_w = (const float*)d_in[9];
    const float* wkv_b_w   = (const float*)d_in[10];
    const float* wo_w      = (const float*)d_in[11];
    const float* wo_b      = (const float*)d_in[12];
    float* out = (float*)d_out;

    float *projcat, *qlat, *kvn, *qhp, *khp, *vhp, *vv, *worn, *wkvbv, *wcat, *bcat, *wqbp, *bqp, *wkp;
    cudaGetSymbolAddress((void**)&projcat, g_projcat);
    cudaGetSymbolAddress((void**)&qlat,  g_qlat);
    cudaGetSymbolAddress((void**)&kvn,   g_kvn);
    cudaGetSymbolAddress((void**)&qhp,   g_qh);
    cudaGetSymbolAddress((void**)&khp,   g_kh);
    cudaGetSymbolAddress((void**)&vhp,   g_vh);
    cudaGetSymbolAddress((void**)&vv,    g_v);
    cudaGetSymbolAddress((void**)&worn,  g_worn);
    cudaGetSymbolAddress((void**)&wkvbv, g_wkvbv);
    cudaGetSymbolAddress((void**)&wcat,  g_wcat);
    cudaGetSymbolAddress((void**)&bcat,  g_bcat);
    cudaGetSymbolAddress((void**)&wqbp,  g_wqbp);
    cudaGetSymbolAddress((void**)&bqp,   g_bqp);
    cudaGetSymbolAddress((void**)&wkp,   g_wkp);

    const int gsm128 = 3*(128+128)*36*4;
    const int gsm96  = 3*(128+96)*36*4;
    const int gsm64  = 3*(128+64)*36*4;
    const int asm_   = (2*BUF + 64*68 + 128)*4;            // 71168
    cudaFuncSetAttribute((tgemm3<128,false,true,false>), cudaFuncAttributeMaxDynamicSharedMemorySize, gsm128);
    cudaFuncSetAttribute((tgemm3<128,true,true,false>),  cudaFuncAttributeMaxDynamicSharedMemorySize, gsm128);
    cudaFuncSetAttribute((tgemm3<128,true,false,false>), cudaFuncAttributeMaxDynamicSharedMemorySize, gsm128);
    cudaFuncSetAttribute((tgemm3<64,true,false,false>),  cudaFuncAttributeMaxDynamicSharedMemorySize, gsm64);
    cudaFuncSetAttribute((tgemm3<96,false,true,true>),   cudaFuncAttributeMaxDynamicSharedMemorySize, gsm96);
    cudaFuncSetAttribute(attn_tc, cudaFuncAttributeMaxDynamicSharedMemorySize, asm_);

    prep_weights<<<1536, 256>>>(wo_w, wkv_b_w, wq_a_w, wq_a_b, wkv_a_w, wkv_a_b,
                                worn, wkvbv, wcat, bcat);
    prep_qk<<<2*NH*QH32, 256>>>(wq_b_w, wq_b_b, wkv_b_w, wqbp, bqp, wkp);

    tgemm3<96,false,true,true><<<dim3(4, NTOK/128, 1), 256, gsm96>>>(
        h_ptr, DIM, 0, wcat, DIM, 0, bcat, projcat, 384, 0, DIM);
    rms2_kernel<<<NTOK/2, 256>>>(projcat, q_norm_w, kv_norm_w, qlat, kvn);

    // per-head q: [8192,256] x [512,256]^T -> qh
    tgemm3<128,true,true,false><<<dim3(4, NTOK/128, 1), 256, gsm128>>>(
        qlat, DLQ, 0, wqbp, DLQ, 0, bqp, qhp, NH*QH32, 0, DLQ);
    // per-head k: [8192,128] x [512,128]^T -> kh
    tgemm3<128,true,false,false><<<dim3(4, NTOK/128, 1), 256, gsm128>>>(
        kvn, DLKV, 0, wkp, DLKV, 0, nullptr, khp, NH*QH32, 0, DLKV);
    // per-head v: vh[:, h*64:(h+1)*64] = kvn @ wkvbv[h]^T
    tgemm3<64,true,false,false><<<dim3(1, NTOK/128, NH), 256, gsm64>>>(
        kvn, DLKV, 0, wkvbv, DLKV, (size_t)NDV*DLKV, nullptr, vhp, NH*NDV, NDV, DLKV);

    // attention (rank-20 scores, 64-dim values)
    attn_tc<<<dim3(SQ/64, NH, BB), 128, asm_>>>(qhp, khp, vhp, vv);

    // out = v @ wo_w^T + wo_b
    tgemm3<128,false,true,false><<<dim3(8, NTOK/128, 1), 256, gsm128>>>(
        vv, NH*NDV, 0, worn, NH*NDV, 0, wo_b, out, DIM, 0, NH*NDV);
}